// round 1
// baseline (speedup 1.0000x reference)
#include <cuda_runtime.h>
#include <math.h>

#define Nn 4096
#define Ee 262144
#define IND 64
#define Hh 128
#define NHEADS 4
#define DHd 32
#define Ll 2

// ---------------- scratch (static device globals; no allocation) -------------
__device__ float g_h[Nn*Hh];
__device__ float g_xp[Nn*Hh];
__device__ float g_als[Nn*NHEADS];
__device__ float g_ald[Nn*NHEADS];
__device__ float g_m[Nn*NHEADS];
__device__ float g_den[Nn*NHEADS];
__device__ float g_e[Ee*NHEADS];
__device__ float g_S[Nn*Hh];
__device__ float g_hloc[Nn*Hh];
__device__ float g_qkv[Nn*3*Hh];
__device__ float g_attn[Nn*Hh];
__device__ float g_tmp[Nn*Hh];
__device__ float g_out[Nn*Hh];
__device__ float g_t1[Nn*2*Hh];
__device__ float g_mlp[Nn*Hh];

__device__ __forceinline__ float bn_scale(float g) { return g * rsqrtf(1.0f + 1e-5f); }

// ---------------- generic tiled GEMM: C[Nr,M] = A[Nr,K] @ B[M,K]^T (+bias)(+relu)
__global__ void gemm_nt(const float* __restrict__ A, const float* __restrict__ B,
                        const float* __restrict__ bias, float* __restrict__ C,
                        int Nr, int M, int K, int relu) {
    __shared__ float As[16][64];
    __shared__ float Bs[16][64];
    const int tx = threadIdx.x, ty = threadIdx.y;
    const int tid = ty * 16 + tx;
    const int r0 = blockIdx.y * 64;
    const int c0 = blockIdx.x * 64;
    float acc[4][4] = {};

    for (int kt = 0; kt < K; kt += 16) {
        // load A tile 64x16 and B tile 64x16 (B guarded by M)
        #pragma unroll
        for (int i = 0; i < 4; i++) {
            int idx = tid + i * 256;          // 0..1023
            int kk = idx & 15;
            int rr = idx >> 4;
            As[kk][rr] = A[(r0 + rr) * K + kt + kk];
            int cc = rr;
            Bs[kk][cc] = (c0 + cc < M) ? B[(c0 + cc) * K + kt + kk] : 0.0f;
        }
        __syncthreads();
        #pragma unroll
        for (int kk = 0; kk < 16; kk++) {
            float a[4], b[4];
            #pragma unroll
            for (int i = 0; i < 4; i++) a[i] = As[kk][ty * 4 + i];
            #pragma unroll
            for (int j = 0; j < 4; j++) b[j] = Bs[kk][tx * 4 + j];
            #pragma unroll
            for (int i = 0; i < 4; i++)
                #pragma unroll
                for (int j = 0; j < 4; j++)
                    acc[i][j] += a[i] * b[j];
        }
        __syncthreads();
    }
    #pragma unroll
    for (int i = 0; i < 4; i++) {
        int r = r0 + ty * 4 + i;
        if (r >= Nr) continue;
        #pragma unroll
        for (int j = 0; j < 4; j++) {
            int c = c0 + tx * 4 + j;
            if (c >= M) continue;
            float v = acc[i][j] + (bias ? bias[c] : 0.0f);
            if (relu) v = fmaxf(v, 0.0f);
            C[r * M + c] = v;
        }
    }
}

// ---------------- GAT kernels ----------------
__global__ void att_logits(const float* __restrict__ asrc, const float* __restrict__ adst) {
    int i = blockIdx.x * blockDim.x + threadIdx.x;
    if (i >= Nn * NHEADS) return;
    int n = i >> 2, hd = i & 3;
    float s = 0.0f, t = 0.0f;
    #pragma unroll
    for (int d = 0; d < DHd; d++) {
        float v = g_xp[n * Hh + hd * DHd + d];
        s += v * asrc[hd * DHd + d];
        t += v * adst[hd * DHd + d];
    }
    g_als[i] = s;
    g_ald[i] = t;
}

__global__ void gat_init() {
    int i = blockIdx.x * blockDim.x + threadIdx.x;
    if (i < Nn * Hh) g_S[i] = 0.0f;
    if (i < Nn * NHEADS) {
        g_m[i] = -INFINITY;
        g_den[i] = 0.0f;
    }
}

__global__ void edge_max(const int* __restrict__ ei) {
    int i = blockIdx.x * blockDim.x + threadIdx.x;
    if (i >= Ee * NHEADS) return;
    int e = i >> 2, hd = i & 3;
    int s = ei[e], d = ei[Ee + e];
    float lg = g_als[s * 4 + hd] + g_ald[d * 4 + hd];
    lg = lg >= 0.0f ? lg : 0.2f * lg;
    float* addr = &g_m[d * 4 + hd];
    if (lg >= 0.0f) atomicMax((int*)addr, __float_as_int(lg));
    else            atomicMin((unsigned int*)addr, __float_as_uint(lg));
}

__global__ void fix_m() {
    int i = blockIdx.x * blockDim.x + threadIdx.x;
    if (i >= Nn * NHEADS) return;
    float m = g_m[i];
    if (!isfinite(m)) g_m[i] = 0.0f;
}

__global__ void edge_exp(const int* __restrict__ ei) {
    int i = blockIdx.x * blockDim.x + threadIdx.x;
    if (i >= Ee * NHEADS) return;
    int e = i >> 2, hd = i & 3;
    int s = ei[e], d = ei[Ee + e];
    float lg = g_als[s * 4 + hd] + g_ald[d * 4 + hd];
    lg = lg >= 0.0f ? lg : 0.2f * lg;
    float ev = __expf(lg - g_m[d * 4 + hd]);
    g_e[i] = ev;
    atomicAdd(&g_den[d * 4 + hd], ev);
}

__global__ void edge_agg(const int* __restrict__ ei) {
    int i = blockIdx.x * blockDim.x + threadIdx.x;
    if (i >= Ee * Hh) return;
    int e = i >> 7;
    int c = i & 127;
    int hd = c >> 5;
    int s = ei[e], d = ei[Ee + e];
    atomicAdd(&g_S[d * Hh + c], g_e[e * 4 + hd] * g_xp[s * Hh + c]);
}

__global__ void gat_final(const float* __restrict__ bias, const float* __restrict__ g0,
                          const float* __restrict__ b0) {
    int i = blockIdx.x * blockDim.x + threadIdx.x;
    if (i >= Nn * Hh) return;
    int c = i & 127, n = i >> 7, hd = c >> 5;
    float v = g_S[i] / (g_den[n * 4 + hd] + 1e-16f) + bias[c] + g_h[i];
    g_hloc[i] = v * bn_scale(g0[c]) + b0[c];
}

// ---------------- flash attention (fp32, online softmax) ----------------
__global__ void flash_attn() {
    const int hd = blockIdx.y;
    const int n = blockIdx.x * 128 + threadIdx.x;
    __shared__ float Ks[64][32];
    __shared__ float Vs[64][32];
    float q[DHd];
    const float scale = rsqrtf((float)DHd);
    #pragma unroll
    for (int d = 0; d < DHd; d++) q[d] = g_qkv[n * 384 + hd * DHd + d] * scale;
    float mx = -INFINITY, lsum = 0.0f;
    float acc[DHd] = {};
    for (int kb = 0; kb < Nn; kb += 64) {
        __syncthreads();
        for (int idx = threadIdx.x; idx < 64 * 32; idx += 128) {
            int j = idx >> 5, d = idx & 31;
            Ks[j][d] = g_qkv[(kb + j) * 384 + 128 + hd * DHd + d];
            Vs[j][d] = g_qkv[(kb + j) * 384 + 256 + hd * DHd + d];
        }
        __syncthreads();
        #pragma unroll 4
        for (int j = 0; j < 64; j++) {
            float s = 0.0f;
            #pragma unroll
            for (int d = 0; d < DHd; d++) s += q[d] * Ks[j][d];
            if (s > mx) {
                float sc = __expf(mx - s);
                lsum *= sc;
                #pragma unroll
                for (int d = 0; d < DHd; d++) acc[d] *= sc;
                mx = s;
            }
            float p = __expf(s - mx);
            lsum += p;
            #pragma unroll
            for (int d = 0; d < DHd; d++) acc[d] += p * Vs[j][d];
        }
    }
    float inv = 1.0f / lsum;
    #pragma unroll
    for (int d = 0; d < DHd; d++) g_attn[n * 128 + hd * DHd + d] = acc[d] * inv;
}

// ---------------- elementwise combiners ----------------
__global__ void combine_att(const float* __restrict__ g1, const float* __restrict__ b1) {
    int i = blockIdx.x * blockDim.x + threadIdx.x;
    if (i >= Nn * Hh) return;
    int c = i & 127;
    float ha = (g_tmp[i] + g_h[i]) * bn_scale(g1[c]) + b1[c];
    g_out[i] = g_hloc[i] + ha;
}

__global__ void final_combine(const float* __restrict__ g2, const float* __restrict__ b2) {
    int i = blockIdx.x * blockDim.x + threadIdx.x;
    if (i >= Nn * Hh) return;
    int c = i & 127;
    float o2 = (g_out[i] + g_mlp[i]) * bn_scale(g2[c]) + b2[c];
    float v = o2 + g_h[i];
    g_h[i] = v > 0.0f ? v : 0.0f;
}

// ---------------- host launch ----------------
extern "C" void kernel_launch(void* const* d_in, const int* in_sizes, int n_in,
                              void* d_out, int out_size) {
    const float* x       = (const float*)d_in[0];
    const int*   ei      = (const int*)d_in[1];
    const float* w_in    = (const float*)d_in[2];
    const float* b_in    = (const float*)d_in[3];
    const float* w_gat   = (const float*)d_in[4];
    const float* att_src = (const float*)d_in[5];
    const float* att_dst = (const float*)d_in[6];
    const float* b_gat   = (const float*)d_in[7];
    const float* w_qkv   = (const float*)d_in[8];
    const float* b_qkv   = (const float*)d_in[9];
    const float* w_o     = (const float*)d_in[10];
    const float* b_o     = (const float*)d_in[11];
    const float* bn_g    = (const float*)d_in[12];
    const float* bn_b    = (const float*)d_in[13];
    const float* w1      = (const float*)d_in[14];
    const float* b1      = (const float*)d_in[15];
    const float* w2      = (const float*)d_in[16];
    const float* b2      = (const float*)d_in[17];
    const float* w_out   = (const float*)d_in[18];
    const float* b_out   = (const float*)d_in[19];
    float* out = (float*)d_out;

    float *p_h, *p_xp, *p_qkv, *p_attn, *p_tmp, *p_out, *p_t1, *p_mlp;
    cudaGetSymbolAddress((void**)&p_h,    g_h);
    cudaGetSymbolAddress((void**)&p_xp,   g_xp);
    cudaGetSymbolAddress((void**)&p_qkv,  g_qkv);
    cudaGetSymbolAddress((void**)&p_attn, g_attn);
    cudaGetSymbolAddress((void**)&p_tmp,  g_tmp);
    cudaGetSymbolAddress((void**)&p_out,  g_out);
    cudaGetSymbolAddress((void**)&p_t1,   g_t1);
    cudaGetSymbolAddress((void**)&p_mlp,  g_mlp);

    dim3 gblk(16, 16);
    const int EW = (Nn * Hh + 255) / 256;          // elementwise grid (2048)
    const int EG = (Ee * NHEADS + 255) / 256;      // edge grid (4096)
    const int AG = (Ee * Hh + 255) / 256;          // edge-agg grid (131072)

    // input projection: h = relu(x @ w_in^T + b_in)
    gemm_nt<<<dim3(2, 64), gblk>>>(x, w_in, b_in, p_h, Nn, Hh, IND, 1);

    for (int l = 0; l < Ll; l++) {
        // ---- GAT branch ----
        gemm_nt<<<dim3(2, 64), gblk>>>(p_h, w_gat + l * Hh * Hh, nullptr, p_xp, Nn, Hh, Hh, 0);
        att_logits<<<(Nn * NHEADS + 127) / 128, 128>>>(att_src + l * Hh, att_dst + l * Hh);
        gat_init<<<EW, 256>>>();
        edge_max<<<EG, 256>>>(ei);
        fix_m<<<(Nn * NHEADS + 255) / 256, 256>>>();
        edge_exp<<<EG, 256>>>(ei);
        edge_agg<<<AG, 256>>>(ei);
        gat_final<<<EW, 256>>>(b_gat + l * Hh, bn_g + (l * 3 + 0) * Hh, bn_b + (l * 3 + 0) * Hh);

        // ---- global attention branch ----
        gemm_nt<<<dim3(6, 64), gblk>>>(p_h, w_qkv + l * 3 * Hh * Hh, b_qkv + l * 3 * Hh,
                                       p_qkv, Nn, 3 * Hh, Hh, 0);
        flash_attn<<<dim3(Nn / 128, NHEADS), 128>>>();
        gemm_nt<<<dim3(2, 64), gblk>>>(p_attn, w_o + l * Hh * Hh, b_o + l * Hh,
                                       p_tmp, Nn, Hh, Hh, 0);
        combine_att<<<EW, 256>>>(bn_g + (l * 3 + 1) * Hh, bn_b + (l * 3 + 1) * Hh);

        // ---- MLP ----
        gemm_nt<<<dim3(4, 64), gblk>>>(p_out, w1 + l * 2 * Hh * Hh, b1 + l * 2 * Hh,
                                       p_t1, Nn, 2 * Hh, Hh, 1);
        gemm_nt<<<dim3(2, 64), gblk>>>(p_t1, w2 + l * 2 * Hh * Hh, b2 + l * Hh,
                                       p_mlp, Nn, Hh, 2 * Hh, 0);
        final_combine<<<EW, 256>>>(bn_g + (l * 3 + 2) * Hh, bn_b + (l * 3 + 2) * Hh);
    }

    // output projection: out = h @ w_out^T + b_out  -> [4096, 2]
    gemm_nt<<<dim3(1, 64), gblk>>>(p_h, w_out, b_out, out, Nn, 2, Hh, 0);
}

// round 2
// speedup vs baseline: 1.8436x; 1.8436x over previous
#include <cuda_runtime.h>
#include <math.h>

#define Nn 4096
#define Ee 262144
#define IND 64
#define Hh 128
#define NHEADS 4
#define DHd 32
#define Ll 2

typedef unsigned long long ull;

// ---------------- scratch (static device globals; no allocation) -------------
__device__ float g_h[Nn*Hh];
__device__ float g_xp[Nn*Hh];
__device__ float g_als[Nn*NHEADS];
__device__ float g_ald[Nn*NHEADS];
__device__ float g_hloc[Nn*Hh];
__device__ float g_qkv[Nn*3*Hh];
__device__ float g_attn[Nn*Hh];
__device__ float g_tmp[Nn*Hh];
__device__ float g_out[Nn*Hh];
__device__ float g_t1[Nn*2*Hh];
__device__ float g_mlp[Nn*Hh];
// CSR
__device__ int g_cnt[Nn];
__device__ int g_cursor[Nn];
__device__ int g_rowptr[Nn+1];
__device__ int g_srcs[Ee];

__device__ __forceinline__ float bn_scale(float g) { return g * rsqrtf(1.0f + 1e-5f); }

// ---- f32x2 packed helpers (sm_103a) ----
__device__ __forceinline__ ull pk(float a, float b) {
    ull r; asm("mov.b64 %0,{%1,%2};" : "=l"(r) : "f"(a), "f"(b)); return r;
}
__device__ __forceinline__ void upk(ull v, float& a, float& b) {
    asm("mov.b64 {%0,%1},%2;" : "=f"(a), "=f"(b) : "l"(v));
}
__device__ __forceinline__ ull f2fma(ull a, ull b, ull c) {
    ull d; asm("fma.rn.f32x2 %0,%1,%2,%3;" : "=l"(d) : "l"(a), "l"(b), "l"(c)); return d;
}
__device__ __forceinline__ ull f2mul(ull a, ull b) {
    ull d; asm("mul.rn.f32x2 %0,%1,%2;" : "=l"(d) : "l"(a), "l"(b)); return d;
}
__device__ __forceinline__ void cpa16(void* sdst, const void* gsrc) {
    unsigned s = (unsigned)__cvta_generic_to_shared(sdst);
    asm volatile("cp.async.cg.shared.global [%0],[%1],16;" :: "r"(s), "l"(gsrc));
}

// ---------------- GEMM: C[Nr,M] = A[Nr,K] @ B[M,K]^T (+bias)(+relu), f32x2 core
__global__ void gemm_nt(const float* __restrict__ A, const float* __restrict__ B,
                        const float* __restrict__ bias, float* __restrict__ C,
                        int Nr, int M, int K, int relu) {
    __shared__ float As[16][64];
    __shared__ ull   Bs[16][64];   // duplicated pairs (b,b)
    const int tx = threadIdx.x, ty = threadIdx.y;
    const int tid = ty * 16 + tx;
    const int r0 = blockIdx.y * 64;
    const int c0 = blockIdx.x * 64;
    ull acc[2][4];
    #pragma unroll
    for (int i = 0; i < 2; i++)
        #pragma unroll
        for (int j = 0; j < 4; j++) acc[i][j] = 0ull;

    for (int kt = 0; kt < K; kt += 16) {
        #pragma unroll
        for (int i = 0; i < 4; i++) {
            int idx = tid + i * 256;
            int kk = idx & 15;
            int rr = idx >> 4;
            As[kk][rr] = A[(r0 + rr) * K + kt + kk];
            float bv = (c0 + rr < M) ? B[(c0 + rr) * K + kt + kk] : 0.0f;
            Bs[kk][rr] = pk(bv, bv);
        }
        __syncthreads();
        #pragma unroll
        for (int kk = 0; kk < 16; kk++) {
            ull a01 = *(const ull*)&As[kk][ty * 4];
            ull a23 = *(const ull*)&As[kk][ty * 4 + 2];
            #pragma unroll
            for (int j = 0; j < 4; j++) {
                ull b = Bs[kk][tx + 16 * j];
                acc[0][j] = f2fma(a01, b, acc[0][j]);
                acc[1][j] = f2fma(a23, b, acc[1][j]);
            }
        }
        __syncthreads();
    }
    #pragma unroll
    for (int j = 0; j < 4; j++) {
        int c = c0 + tx + 16 * j;
        if (c >= M) continue;
        float bsv = bias ? bias[c] : 0.0f;
        float v0, v1, v2, v3;
        upk(acc[0][j], v0, v1);
        upk(acc[1][j], v2, v3);
        int r = r0 + ty * 4;
        v0 += bsv; v1 += bsv; v2 += bsv; v3 += bsv;
        if (relu) { v0 = fmaxf(v0,0.f); v1 = fmaxf(v1,0.f); v2 = fmaxf(v2,0.f); v3 = fmaxf(v3,0.f); }
        if (r + 0 < Nr) C[(r + 0) * M + c] = v0;
        if (r + 1 < Nr) C[(r + 1) * M + c] = v1;
        if (r + 2 < Nr) C[(r + 2) * M + c] = v2;
        if (r + 3 < Nr) C[(r + 3) * M + c] = v3;
    }
}

// ---------------- CSR build ----------------
__global__ void csr_hist(const int* __restrict__ ei) {
    int e = blockIdx.x * blockDim.x + threadIdx.x;
    if (e < Ee) atomicAdd(&g_cnt[ei[Ee + e]], 1);
}

__global__ void csr_scan() {   // one block, 1024 threads, 4 elems each
    __shared__ int sm[1024];
    int t = threadIdx.x;
    int b = t * 4;
    int c0 = g_cnt[b], c1 = g_cnt[b+1], c2 = g_cnt[b+2], c3 = g_cnt[b+3];
    int s1 = c0 + c1, s2 = s1 + c2, s3 = s2 + c3;
    sm[t] = s3;
    __syncthreads();
    for (int off = 1; off < 1024; off <<= 1) {
        int v = (t >= off) ? sm[t - off] : 0;
        __syncthreads();
        sm[t] += v;
        __syncthreads();
    }
    int excl = sm[t] - s3;
    g_rowptr[b]   = excl;
    g_rowptr[b+1] = excl + c0;
    g_rowptr[b+2] = excl + s1;
    g_rowptr[b+3] = excl + s2;
    g_cursor[b]   = excl;
    g_cursor[b+1] = excl + c0;
    g_cursor[b+2] = excl + s1;
    g_cursor[b+3] = excl + s2;
    if (t == 1023) g_rowptr[Nn] = sm[1023];
}

__global__ void csr_scatter(const int* __restrict__ ei) {
    int e = blockIdx.x * blockDim.x + threadIdx.x;
    if (e >= Ee) return;
    int d = ei[Ee + e];
    int pos = atomicAdd(&g_cursor[d], 1);
    g_srcs[pos] = ei[e];
}

// ---------------- GAT: per-node attention logits ----------------
__global__ void att_logits(const float* __restrict__ asrc, const float* __restrict__ adst) {
    int i = blockIdx.x * blockDim.x + threadIdx.x;
    if (i >= Nn * NHEADS) return;
    int n = i >> 2, hd = i & 3;
    const float4* xp = (const float4*)&g_xp[n * Hh + hd * DHd];
    const float4* as = (const float4*)&asrc[hd * DHd];
    const float4* ad = (const float4*)&adst[hd * DHd];
    float s = 0.0f, t = 0.0f;
    #pragma unroll
    for (int d4 = 0; d4 < 8; d4++) {
        float4 v = xp[d4], a = as[d4], b = ad[d4];
        s += v.x*a.x + v.y*a.y + v.z*a.z + v.w*a.w;
        t += v.x*b.x + v.y*b.y + v.z*b.z + v.w*b.w;
    }
    g_als[i] = s;
    g_ald[i] = t;
}

__device__ __forceinline__ float leaky(float x) { return x >= 0.0f ? x : 0.2f * x; }

// ---------------- fused GAT: block = one dst node, 128 threads (channel) ----
__global__ void gat_fused(const float* __restrict__ bias, const float* __restrict__ g0,
                          const float* __restrict__ b0) {
    __shared__ int    s_src[128];
    __shared__ float  s_w[128][4];
    __shared__ float4 s_red[128];
    const int d = blockIdx.x;
    const int t = threadIdx.x;
    const int head = t >> 5;
    const int beg = g_rowptr[d], end = g_rowptr[d + 1];
    const float4 ad4 = *(const float4*)&g_ald[d * 4];

    // pass 1: per-head max of leaky logits
    const float NEGINF = -__int_as_float(0x7f800000);
    float4 mx = make_float4(NEGINF, NEGINF, NEGINF, NEGINF);
    for (int e = beg + t; e < end; e += 128) {
        int s = g_srcs[e];
        float4 as = *(const float4*)&g_als[s * 4];
        mx.x = fmaxf(mx.x, leaky(as.x + ad4.x));
        mx.y = fmaxf(mx.y, leaky(as.y + ad4.y));
        mx.z = fmaxf(mx.z, leaky(as.z + ad4.z));
        mx.w = fmaxf(mx.w, leaky(as.w + ad4.w));
    }
    s_red[t] = mx;
    __syncthreads();
    for (int off = 64; off > 0; off >>= 1) {
        if (t < off) {
            float4 a = s_red[t], b = s_red[t + off];
            s_red[t] = make_float4(fmaxf(a.x,b.x), fmaxf(a.y,b.y), fmaxf(a.z,b.z), fmaxf(a.w,b.w));
        }
        __syncthreads();
    }
    const float4 m4 = s_red[0];
    __syncthreads();

    // pass 2: chunks of 128 edges: weights + accumulation
    float4 den = make_float4(0,0,0,0);
    float acc = 0.0f;
    for (int cb = beg; cb < end; cb += 128) {
        int cnt = min(128, end - cb);
        if (t < cnt) {
            int s = g_srcs[cb + t];
            s_src[t] = s;
            float4 as = *(const float4*)&g_als[s * 4];
            float w0 = __expf(leaky(as.x + ad4.x) - m4.x);
            float w1 = __expf(leaky(as.y + ad4.y) - m4.y);
            float w2 = __expf(leaky(as.z + ad4.z) - m4.z);
            float w3 = __expf(leaky(as.w + ad4.w) - m4.w);
            s_w[t][0] = w0; s_w[t][1] = w1; s_w[t][2] = w2; s_w[t][3] = w3;
            den.x += w0; den.y += w1; den.z += w2; den.w += w3;
        }
        __syncthreads();
        #pragma unroll 4
        for (int i = 0; i < cnt; i++)
            acc = fmaf(s_w[i][head], g_xp[s_src[i] * Hh + t], acc);
        __syncthreads();
    }
    s_red[t] = den;
    __syncthreads();
    for (int off = 64; off > 0; off >>= 1) {
        if (t < off) {
            float4 a = s_red[t], b = s_red[t + off];
            s_red[t] = make_float4(a.x+b.x, a.y+b.y, a.z+b.z, a.w+b.w);
        }
        __syncthreads();
    }
    float4 den4 = s_red[0];
    float denh = head == 0 ? den4.x : head == 1 ? den4.y : head == 2 ? den4.z : den4.w;
    float v = acc / (denh + 1e-16f) + bias[t] + g_h[d * Hh + t];
    g_hloc[d * Hh + t] = v * bn_scale(g0[t]) + b0[t];
}

// ---------------- flash attention: f32x2 + cp.async double buffer ------------
__global__ void __launch_bounds__(64) flash_attn() {
    __shared__ ulonglong2 Ks[2][64][8];
    __shared__ ulonglong2 Vs[2][64][8];
    const int hd = blockIdx.y;
    const int t = threadIdx.x;
    const int n = blockIdx.x * 64 + t;

    ull q2[16];
    {
        const float sc = 0.17677669529663687f;   // 1/sqrt(32)
        ull scp = pk(sc, sc);
        const ulonglong2* qp = (const ulonglong2*)&g_qkv[n * 384 + hd * DHd];
        #pragma unroll
        for (int i = 0; i < 8; i++) {
            ulonglong2 v = qp[i];
            q2[2*i]   = f2mul(v.x, scp);
            q2[2*i+1] = f2mul(v.y, scp);
        }
    }

    // tile loader: 64 keys x 32 floats for K and V
    auto load_tile = [&](int kb, int buf) {
        #pragma unroll
        for (int idx = t; idx < 512; idx += 64) {
            int j = idx >> 3, d4 = idx & 7;
            const float* kp = &g_qkv[(kb + j) * 384 + 128 + hd * DHd + d4 * 4];
            cpa16(&Ks[buf][j][d4], kp);
            cpa16(&Vs[buf][j][d4], kp + 128);
        }
        asm volatile("cp.async.commit_group;");
    };

    load_tile(0, 0);
    float mx = -__int_as_float(0x7f800000);
    float lsum = 0.0f;
    ull acc2[16];
    #pragma unroll
    for (int i = 0; i < 16; i++) acc2[i] = 0ull;

    for (int kb = 0; kb < Nn; kb += 64) {
        int buf = (kb >> 6) & 1;
        bool more = (kb + 64 < Nn);
        if (more) load_tile(kb + 64, buf ^ 1);
        if (more) asm volatile("cp.async.wait_group 1;");
        else      asm volatile("cp.async.wait_group 0;");
        __syncthreads();

        #pragma unroll 2
        for (int j = 0; j < 64; j++) {
            ull s2a = 0ull, s2b = 0ull;
            #pragma unroll
            for (int d4 = 0; d4 < 8; d4++) {
                ulonglong2 kk = Ks[buf][j][d4];
                s2a = f2fma(q2[2*d4],   kk.x, s2a);
                s2b = f2fma(q2[2*d4+1], kk.y, s2b);
            }
            float a0, a1, b0, b1;
            upk(s2a, a0, a1); upk(s2b, b0, b1);
            float s = (a0 + a1) + (b0 + b1);
            if (s > mx) {
                float c = __expf(mx - s);
                lsum *= c;
                ull c2 = pk(c, c);
                #pragma unroll
                for (int i = 0; i < 16; i++) acc2[i] = f2mul(acc2[i], c2);
                mx = s;
            }
            float p = __expf(s - mx);
            lsum += p;
            ull p2 = pk(p, p);
            #pragma unroll
            for (int d4 = 0; d4 < 8; d4++) {
                ulonglong2 vv = Vs[buf][j][d4];
                acc2[2*d4]   = f2fma(p2, vv.x, acc2[2*d4]);
                acc2[2*d4+1] = f2fma(p2, vv.y, acc2[2*d4+1]);
            }
        }
        __syncthreads();
    }

    float inv = 1.0f / lsum;
    ull invp = pk(inv, inv);
    ulonglong2* op = (ulonglong2*)&g_attn[n * Hh + hd * DHd];
    #pragma unroll
    for (int i = 0; i < 8; i++) {
        ulonglong2 o;
        o.x = f2mul(acc2[2*i],   invp);
        o.y = f2mul(acc2[2*i+1], invp);
        op[i] = o;
    }
}

// ---------------- elementwise combiners (float4) ----------------
__global__ void combine_att(const float4* __restrict__ g1, const float4* __restrict__ b1) {
    int i = blockIdx.x * blockDim.x + threadIdx.x;
    if (i >= Nn * Hh / 4) return;
    int c4 = i & 31;
    float4 gg = g1[c4], bb = b1[c4];
    float4 tm = ((const float4*)g_tmp)[i];
    float4 hh = ((const float4*)g_h)[i];
    float4 hl = ((const float4*)g_hloc)[i];
    float4 o;
    o.x = hl.x + (tm.x + hh.x) * bn_scale(gg.x) + bb.x;
    o.y = hl.y + (tm.y + hh.y) * bn_scale(gg.y) + bb.y;
    o.z = hl.z + (tm.z + hh.z) * bn_scale(gg.z) + bb.z;
    o.w = hl.w + (tm.w + hh.w) * bn_scale(gg.w) + bb.w;
    ((float4*)g_out)[i] = o;
}

__global__ void final_combine(const float4* __restrict__ g2, const float4* __restrict__ b2) {
    int i = blockIdx.x * blockDim.x + threadIdx.x;
    if (i >= Nn * Hh / 4) return;
    int c4 = i & 31;
    float4 gg = g2[c4], bb = b2[c4];
    float4 ou = ((const float4*)g_out)[i];
    float4 ml = ((const float4*)g_mlp)[i];
    float4 hh = ((const float4*)g_h)[i];
    float4 r;
    r.x = fmaxf((ou.x + ml.x) * bn_scale(gg.x) + bb.x + hh.x, 0.0f);
    r.y = fmaxf((ou.y + ml.y) * bn_scale(gg.y) + bb.y + hh.y, 0.0f);
    r.z = fmaxf((ou.z + ml.z) * bn_scale(gg.z) + bb.z + hh.z, 0.0f);
    r.w = fmaxf((ou.w + ml.w) * bn_scale(gg.w) + bb.w + hh.w, 0.0f);
    ((float4*)g_h)[i] = r;
}

// ---------------- host launch ----------------
extern "C" void kernel_launch(void* const* d_in, const int* in_sizes, int n_in,
                              void* d_out, int out_size) {
    const float* x       = (const float*)d_in[0];
    const int*   ei      = (const int*)d_in[1];
    const float* w_in    = (const float*)d_in[2];
    const float* b_in    = (const float*)d_in[3];
    const float* w_gat   = (const float*)d_in[4];
    const float* att_src = (const float*)d_in[5];
    const float* att_dst = (const float*)d_in[6];
    const float* b_gat   = (const float*)d_in[7];
    const float* w_qkv   = (const float*)d_in[8];
    const float* b_qkv   = (const float*)d_in[9];
    const float* w_o     = (const float*)d_in[10];
    const float* b_o     = (const float*)d_in[11];
    const float* bn_g    = (const float*)d_in[12];
    const float* bn_b    = (const float*)d_in[13];
    const float* w1      = (const float*)d_in[14];
    const float* b1      = (const float*)d_in[15];
    const float* w2      = (const float*)d_in[16];
    const float* b2      = (const float*)d_in[17];
    const float* w_out   = (const float*)d_in[18];
    const float* b_out   = (const float*)d_in[19];
    float* out = (float*)d_out;

    float *p_h, *p_xp, *p_qkv, *p_attn, *p_tmp, *p_out, *p_t1, *p_mlp;
    int* p_cnt;
    cudaGetSymbolAddress((void**)&p_h,    g_h);
    cudaGetSymbolAddress((void**)&p_xp,   g_xp);
    cudaGetSymbolAddress((void**)&p_qkv,  g_qkv);
    cudaGetSymbolAddress((void**)&p_attn, g_attn);
    cudaGetSymbolAddress((void**)&p_tmp,  g_tmp);
    cudaGetSymbolAddress((void**)&p_out,  g_out);
    cudaGetSymbolAddress((void**)&p_t1,   g_t1);
    cudaGetSymbolAddress((void**)&p_mlp,  g_mlp);
    cudaGetSymbolAddress((void**)&p_cnt,  g_cnt);

    dim3 gblk(16, 16);
    const int EW4 = (Nn * Hh / 4 + 255) / 256;

    // CSR build (per-launch, layer-independent)
    cudaMemsetAsync(p_cnt, 0, Nn * sizeof(int));
    csr_hist<<<(Ee + 255) / 256, 256>>>(ei);
    csr_scan<<<1, 1024>>>();
    csr_scatter<<<(Ee + 255) / 256, 256>>>(ei);

    // input projection: h = relu(x @ w_in^T + b_in)
    gemm_nt<<<dim3(2, 64), gblk>>>(x, w_in, b_in, p_h, Nn, Hh, IND, 1);

    for (int l = 0; l < Ll; l++) {
        // ---- GAT branch ----
        gemm_nt<<<dim3(2, 64), gblk>>>(p_h, w_gat + l * Hh * Hh, nullptr, p_xp, Nn, Hh, Hh, 0);
        att_logits<<<(Nn * NHEADS + 127) / 128, 128>>>(att_src + l * Hh, att_dst + l * Hh);
        gat_fused<<<Nn, 128>>>(b_gat + l * Hh, bn_g + (l * 3 + 0) * Hh, bn_b + (l * 3 + 0) * Hh);

        // ---- global attention branch ----
        gemm_nt<<<dim3(6, 64), gblk>>>(p_h, w_qkv + l * 3 * Hh * Hh, b_qkv + l * 3 * Hh,
                                       p_qkv, Nn, 3 * Hh, Hh, 0);
        flash_attn<<<dim3(Nn / 64, NHEADS), 64>>>();
        gemm_nt<<<dim3(2, 64), gblk>>>(p_attn, w_o + l * Hh * Hh, b_o + l * Hh,
                                       p_tmp, Nn, Hh, Hh, 0);
        combine_att<<<EW4, 256>>>((const float4*)(bn_g + (l * 3 + 1) * Hh),
                                  (const float4*)(bn_b + (l * 3 + 1) * Hh));

        // ---- MLP ----
        gemm_nt<<<dim3(4, 64), gblk>>>(p_out, w1 + l * 2 * Hh * Hh, b1 + l * 2 * Hh,
                                       p_t1, Nn, 2 * Hh, Hh, 1);
        gemm_nt<<<dim3(2, 64), gblk>>>(p_t1, w2 + l * 2 * Hh * Hh, b2 + l * Hh,
                                       p_mlp, Nn, Hh, 2 * Hh, 0);
        final_combine<<<EW4, 256>>>((const float4*)(bn_g + (l * 3 + 2) * Hh),
                                    (const float4*)(bn_b + (l * 3 + 2) * Hh));
    }

    // output projection -> [4096, 2]
    gemm_nt<<<dim3(1, 64), gblk>>>(p_h, w_out, b_out, out, Nn, 2, Hh, 0);
}

// round 3
// speedup vs baseline: 2.3874x; 1.2949x over previous
#include <cuda_runtime.h>
#include <math.h>

#define Nn 4096
#define Ee 262144
#define IND 64
#define Hh 128
#define NHEADS 4
#define DHd 32
#define Ll 2
#define KSPLIT 4
#define NQH (Nn * NHEADS)

typedef unsigned long long ull;

// ---------------- scratch (static device globals; no allocation) -------------
__device__ float g_h[Nn*Hh];
__device__ float g_xp[Nn*Hh];
__device__ float g_als[Nn*NHEADS];
__device__ float g_ald[Nn*NHEADS];
__device__ float g_hloc[Nn*Hh];
__device__ float g_qkv[Nn*3*Hh];
__device__ float g_attn[Nn*Hh];
__device__ float g_tmp[Nn*Hh];
__device__ float g_out[Nn*Hh];
__device__ float g_t1[Nn*2*Hh];
__device__ float g_mlp[Nn*Hh];
// flash split-K partials
__device__ float g_pm[KSPLIT*NQH];
__device__ float g_pl[KSPLIT*NQH];
__device__ float g_pacc[KSPLIT*NQH*DHd];
// CSR
__device__ int g_cnt[Nn];
__device__ int g_cursor[Nn];
__device__ int g_rowptr[Nn+1];
__device__ int g_srcs[Ee];

__device__ __forceinline__ float bn_scale(float g) { return g * rsqrtf(1.0f + 1e-5f); }

// ---- f32x2 packed helpers (sm_103a) ----
__device__ __forceinline__ ull pk(float a, float b) {
    ull r; asm("mov.b64 %0,{%1,%2};" : "=l"(r) : "f"(a), "f"(b)); return r;
}
__device__ __forceinline__ void upk(ull v, float& a, float& b) {
    asm("mov.b64 {%0,%1},%2;" : "=f"(a), "=f"(b) : "l"(v));
}
__device__ __forceinline__ ull f2fma(ull a, ull b, ull c) {
    ull d; asm("fma.rn.f32x2 %0,%1,%2,%3;" : "=l"(d) : "l"(a), "l"(b), "l"(c)); return d;
}
__device__ __forceinline__ ull f2mul(ull a, ull b) {
    ull d; asm("mul.rn.f32x2 %0,%1,%2;" : "=l"(d) : "l"(a), "l"(b)); return d;
}
__device__ __forceinline__ void cpa16(void* sdst, const void* gsrc) {
    unsigned s = (unsigned)__cvta_generic_to_shared(sdst);
    asm volatile("cp.async.cg.shared.global [%0],[%1],16;" :: "r"(s), "l"(gsrc));
}

// ---------------- GEMM with optional second weight matrix --------------------
// C1[Nr,M1] = A[Nr,K] @ B1[M1,K]^T (+bias1)   for cols [0,M1)
// C2[Nr,M2] = A[Nr,K] @ B2[M2,K]^T (+bias2)   for cols [M1,M1+M2)
__global__ void gemm_nt(const float* __restrict__ A,
                        const float* __restrict__ B1, const float* __restrict__ bias1,
                        float* __restrict__ C1, int M1,
                        const float* __restrict__ B2, const float* __restrict__ bias2,
                        float* __restrict__ C2, int M2,
                        int Nr, int K, int relu) {
    __shared__ float As[16][66];
    __shared__ ull   Bs[16][66];   // duplicated pairs (b,b)
    const int tx = threadIdx.x, ty = threadIdx.y;
    const int tid = ty * 16 + tx;
    const int r0 = blockIdx.y * 64;
    const int c0 = blockIdx.x * 64;
    const int Mtot = M1 + M2;
    ull acc[2][4];
    #pragma unroll
    for (int i = 0; i < 2; i++)
        #pragma unroll
        for (int j = 0; j < 4; j++) acc[i][j] = 0ull;

    for (int kt = 0; kt < K; kt += 16) {
        #pragma unroll
        for (int i = 0; i < 4; i++) {
            int idx = tid + i * 256;
            int kk = idx & 15;
            int rr = idx >> 4;
            As[kk][rr] = A[(r0 + rr) * K + kt + kk];
            int cc = c0 + rr;
            float bv = 0.0f;
            if (cc < Mtot) {
                const float* Brow = (cc < M1) ? (B1 + (size_t)cc * K)
                                              : (B2 + (size_t)(cc - M1) * K);
                bv = Brow[kt + kk];
            }
            Bs[kk][rr] = pk(bv, bv);
        }
        __syncthreads();
        #pragma unroll
        for (int kk = 0; kk < 16; kk++) {
            ull a01 = *(const ull*)&As[kk][ty * 4];
            ull a23 = *(const ull*)&As[kk][ty * 4 + 2];
            #pragma unroll
            for (int j = 0; j < 4; j++) {
                ull b = Bs[kk][tx + 16 * j];
                acc[0][j] = f2fma(a01, b, acc[0][j]);
                acc[1][j] = f2fma(a23, b, acc[1][j]);
            }
        }
        __syncthreads();
    }
    #pragma unroll
    for (int j = 0; j < 4; j++) {
        int c = c0 + tx + 16 * j;
        if (c >= Mtot) continue;
        float bsv;
        float* Cp;
        int ld;
        int cc;
        if (c < M1) { bsv = bias1 ? bias1[c] : 0.0f; Cp = C1; ld = M1; cc = c; }
        else        { bsv = bias2 ? bias2[c - M1] : 0.0f; Cp = C2; ld = M2; cc = c - M1; }
        float v0, v1, v2, v3;
        upk(acc[0][j], v0, v1);
        upk(acc[1][j], v2, v3);
        int r = r0 + ty * 4;
        v0 += bsv; v1 += bsv; v2 += bsv; v3 += bsv;
        if (relu) { v0 = fmaxf(v0,0.f); v1 = fmaxf(v1,0.f); v2 = fmaxf(v2,0.f); v3 = fmaxf(v3,0.f); }
        Cp[(size_t)(r + 0) * ld + cc] = v0;
        Cp[(size_t)(r + 1) * ld + cc] = v1;
        Cp[(size_t)(r + 2) * ld + cc] = v2;
        Cp[(size_t)(r + 3) * ld + cc] = v3;
    }
}

// ---------------- CSR build ----------------
__global__ void csr_hist(const int* __restrict__ ei) {
    int e = blockIdx.x * blockDim.x + threadIdx.x;
    if (e < Ee) atomicAdd(&g_cnt[ei[Ee + e]], 1);
}

__global__ void csr_scan() {   // one block, 1024 threads, 4 elems each
    __shared__ int sm[1024];
    int t = threadIdx.x;
    int b = t * 4;
    int c0 = g_cnt[b], c1 = g_cnt[b+1], c2 = g_cnt[b+2], c3 = g_cnt[b+3];
    int s1 = c0 + c1, s2 = s1 + c2, s3 = s2 + c3;
    sm[t] = s3;
    __syncthreads();
    for (int off = 1; off < 1024; off <<= 1) {
        int v = (t >= off) ? sm[t - off] : 0;
        __syncthreads();
        sm[t] += v;
        __syncthreads();
    }
    int excl = sm[t] - s3;
    g_rowptr[b]   = excl;
    g_rowptr[b+1] = excl + c0;
    g_rowptr[b+2] = excl + s1;
    g_rowptr[b+3] = excl + s2;
    g_cursor[b]   = excl;
    g_cursor[b+1] = excl + c0;
    g_cursor[b+2] = excl + s1;
    g_cursor[b+3] = excl + s2;
    if (t == 1023) g_rowptr[Nn] = sm[1023];
}

__global__ void csr_scatter(const int* __restrict__ ei) {
    int e = blockIdx.x * blockDim.x + threadIdx.x;
    if (e >= Ee) return;
    int d = ei[Ee + e];
    int pos = atomicAdd(&g_cursor[d], 1);
    g_srcs[pos] = ei[e];
}

// ---------------- GAT: per-node attention logits ----------------
__global__ void att_logits(const float* __restrict__ asrc, const float* __restrict__ adst) {
    int i = blockIdx.x * blockDim.x + threadIdx.x;
    if (i >= Nn * NHEADS) return;
    int n = i >> 2, hd = i & 3;
    const float4* xp = (const float4*)&g_xp[n * Hh + hd * DHd];
    const float4* as = (const float4*)&asrc[hd * DHd];
    const float4* ad = (const float4*)&adst[hd * DHd];
    float s = 0.0f, t = 0.0f;
    #pragma unroll
    for (int d4 = 0; d4 < 8; d4++) {
        float4 v = xp[d4], a = as[d4], b = ad[d4];
        s += v.x*a.x + v.y*a.y + v.z*a.z + v.w*a.w;
        t += v.x*b.x + v.y*b.y + v.z*b.z + v.w*b.w;
    }
    g_als[i] = s;
    g_ald[i] = t;
}

__device__ __forceinline__ float leaky(float x) { return x >= 0.0f ? x : 0.2f * x; }

// ---------------- fused GAT: block = one dst node, 128 threads (channel) ----
__global__ void gat_fused(const float* __restrict__ bias, const float* __restrict__ g0,
                          const float* __restrict__ b0) {
    __shared__ int    s_src[128];
    __shared__ float  s_w[128][4];
    __shared__ float4 s_red[128];
    const int d = blockIdx.x;
    const int t = threadIdx.x;
    const int head = t >> 5;
    const int beg = g_rowptr[d], end = g_rowptr[d + 1];
    const float4 ad4 = *(const float4*)&g_ald[d * 4];

    // pass 1: per-head max of leaky logits
    const float NEGINF = -__int_as_float(0x7f800000);
    float4 mx = make_float4(NEGINF, NEGINF, NEGINF, NEGINF);
    for (int e = beg + t; e < end; e += 128) {
        int s = g_srcs[e];
        float4 as = *(const float4*)&g_als[s * 4];
        mx.x = fmaxf(mx.x, leaky(as.x + ad4.x));
        mx.y = fmaxf(mx.y, leaky(as.y + ad4.y));
        mx.z = fmaxf(mx.z, leaky(as.z + ad4.z));
        mx.w = fmaxf(mx.w, leaky(as.w + ad4.w));
    }
    s_red[t] = mx;
    __syncthreads();
    for (int off = 64; off > 0; off >>= 1) {
        if (t < off) {
            float4 a = s_red[t], b = s_red[t + off];
            s_red[t] = make_float4(fmaxf(a.x,b.x), fmaxf(a.y,b.y), fmaxf(a.z,b.z), fmaxf(a.w,b.w));
        }
        __syncthreads();
    }
    const float4 m4 = s_red[0];
    __syncthreads();

    // pass 2: chunks of 128 edges: weights + accumulation
    float4 den = make_float4(0,0,0,0);
    float acc = 0.0f;
    for (int cb = beg; cb < end; cb += 128) {
        int cnt = min(128, end - cb);
        if (t < cnt) {
            int s = g_srcs[cb + t];
            s_src[t] = s;
            float4 as = *(const float4*)&g_als[s * 4];
            float w0 = __expf(leaky(as.x + ad4.x) - m4.x);
            float w1 = __expf(leaky(as.y + ad4.y) - m4.y);
            float w2 = __expf(leaky(as.z + ad4.z) - m4.z);
            float w3 = __expf(leaky(as.w + ad4.w) - m4.w);
            s_w[t][0] = w0; s_w[t][1] = w1; s_w[t][2] = w2; s_w[t][3] = w3;
            den.x += w0; den.y += w1; den.z += w2; den.w += w3;
        }
        __syncthreads();
        #pragma unroll 4
        for (int i = 0; i < cnt; i++)
            acc = fmaf(s_w[i][head], g_xp[s_src[i] * Hh + t], acc);
        __syncthreads();
    }
    s_red[t] = den;
    __syncthreads();
    for (int off = 64; off > 0; off >>= 1) {
        if (t < off) {
            float4 a = s_red[t], b = s_red[t + off];
            s_red[t] = make_float4(a.x+b.x, a.y+b.y, a.z+b.z, a.w+b.w);
        }
        __syncthreads();
    }
    float4 den4 = s_red[0];
    float denh = head == 0 ? den4.x : head == 1 ? den4.y : head == 2 ? den4.z : den4.w;
    float v = acc / (denh + 1e-16f) + bias[t] + g_h[d * Hh + t];
    g_hloc[d * Hh + t] = v * bn_scale(g0[t]) + b0[t];
}

// ---------------- flash attention: split-K, f32x2, cp.async double buffer ----
__global__ void __launch_bounds__(64) flash_attn() {
    __shared__ ulonglong2 Ks[2][64][8];
    __shared__ ulonglong2 Vs[2][64][8];
    const int hd = blockIdx.y;
    const int sp = blockIdx.z;
    const int t = threadIdx.x;
    const int n = blockIdx.x * 64 + t;
    const int kbase = sp * (Nn / KSPLIT);   // 1024 keys per split
    const int kend  = kbase + Nn / KSPLIT;

    ull q2[16];
    {
        const float sc = 0.17677669529663687f;   // 1/sqrt(32)
        ull scp = pk(sc, sc);
        const ulonglong2* qp = (const ulonglong2*)&g_qkv[n * 384 + hd * DHd];
        #pragma unroll
        for (int i = 0; i < 8; i++) {
            ulonglong2 v = qp[i];
            q2[2*i]   = f2mul(v.x, scp);
            q2[2*i+1] = f2mul(v.y, scp);
        }
    }

    auto load_tile = [&](int kb, int buf) {
        #pragma unroll
        for (int idx = t; idx < 512; idx += 64) {
            int j = idx >> 3, d4 = idx & 7;
            const float* kp = &g_qkv[(kb + j) * 384 + 128 + hd * DHd + d4 * 4];
            cpa16(&Ks[buf][j][d4], kp);
            cpa16(&Vs[buf][j][d4], kp + 128);
        }
        asm volatile("cp.async.commit_group;");
    };

    load_tile(kbase, 0);
    float mx = -__int_as_float(0x7f800000);
    float lsum = 0.0f;
    ull acc2[16];
    #pragma unroll
    for (int i = 0; i < 16; i++) acc2[i] = 0ull;

    for (int kb = kbase; kb < kend; kb += 64) {
        int buf = ((kb - kbase) >> 6) & 1;
        bool more = (kb + 64 < kend);
        if (more) load_tile(kb + 64, buf ^ 1);
        if (more) asm volatile("cp.async.wait_group 1;");
        else      asm volatile("cp.async.wait_group 0;");
        __syncthreads();

        #pragma unroll 2
        for (int j = 0; j < 64; j++) {
            ull s2a = 0ull, s2b = 0ull;
            #pragma unroll
            for (int d4 = 0; d4 < 8; d4++) {
                ulonglong2 kk = Ks[buf][j][d4];
                s2a = f2fma(q2[2*d4],   kk.x, s2a);
                s2b = f2fma(q2[2*d4+1], kk.y, s2b);
            }
            float a0, a1, b0, b1;
            upk(s2a, a0, a1); upk(s2b, b0, b1);
            float s = (a0 + a1) + (b0 + b1);
            if (s > mx) {
                float c = __expf(mx - s);
                lsum *= c;
                ull c2 = pk(c, c);
                #pragma unroll
                for (int i = 0; i < 16; i++) acc2[i] = f2mul(acc2[i], c2);
                mx = s;
            }
            float p = __expf(s - mx);
            lsum += p;
            ull p2 = pk(p, p);
            #pragma unroll
            for (int d4 = 0; d4 < 8; d4++) {
                ulonglong2 vv = Vs[buf][j][d4];
                acc2[2*d4]   = f2fma(p2, vv.x, acc2[2*d4]);
                acc2[2*d4+1] = f2fma(p2, vv.y, acc2[2*d4+1]);
            }
        }
        __syncthreads();
    }

    const int qh = n * NHEADS + hd;
    g_pm[sp * NQH + qh] = mx;
    g_pl[sp * NQH + qh] = lsum;
    ulonglong2* op = (ulonglong2*)&g_pacc[((size_t)sp * NQH + qh) * DHd];
    #pragma unroll
    for (int i = 0; i < 8; i++) {
        ulonglong2 o;
        o.x = acc2[2*i];
        o.y = acc2[2*i+1];
        op[i] = o;
    }
}

// merge split-K partials: thread per (qh, d)
__global__ void flash_merge() {
    int i = blockIdx.x * blockDim.x + threadIdx.x;
    if (i >= NQH * DHd) return;
    int qh = i >> 5;
    int d = i & 31;
    float m0 = g_pm[0*NQH+qh], m1 = g_pm[1*NQH+qh];
    float m2 = g_pm[2*NQH+qh], m3 = g_pm[3*NQH+qh];
    float M = fmaxf(fmaxf(m0, m1), fmaxf(m2, m3));
    float w0 = __expf(m0 - M), w1 = __expf(m1 - M);
    float w2 = __expf(m2 - M), w3 = __expf(m3 - M);
    float L = g_pl[0*NQH+qh]*w0 + g_pl[1*NQH+qh]*w1 + g_pl[2*NQH+qh]*w2 + g_pl[3*NQH+qh]*w3;
    float a = g_pacc[((size_t)0*NQH+qh)*DHd + d] * w0
            + g_pacc[((size_t)1*NQH+qh)*DHd + d] * w1
            + g_pacc[((size_t)2*NQH+qh)*DHd + d] * w2
            + g_pacc[((size_t)3*NQH+qh)*DHd + d] * w3;
    int n = qh >> 2, hd = qh & 3;
    g_attn[n * Hh + hd * DHd + d] = a / L;
}

// ---------------- elementwise combiners (float4) ----------------
__global__ void combine_att(const float4* __restrict__ g1, const float4* __restrict__ b1) {
    int i = blockIdx.x * blockDim.x + threadIdx.x;
    if (i >= Nn * Hh / 4) return;
    int c4 = i & 31;
    float4 gg = g1[c4], bb = b1[c4];
    float4 tm = ((const float4*)g_tmp)[i];
    float4 hh = ((const float4*)g_h)[i];
    float4 hl = ((const float4*)g_hloc)[i];
    float4 o;
    o.x = hl.x + (tm.x + hh.x) * bn_scale(gg.x) + bb.x;
    o.y = hl.y + (tm.y + hh.y) * bn_scale(gg.y) + bb.y;
    o.z = hl.z + (tm.z + hh.z) * bn_scale(gg.z) + bb.z;
    o.w = hl.w + (tm.w + hh.w) * bn_scale(gg.w) + bb.w;
    ((float4*)g_out)[i] = o;
}

__global__ void final_combine(const float4* __restrict__ g2, const float4* __restrict__ b2) {
    int i = blockIdx.x * blockDim.x + threadIdx.x;
    if (i >= Nn * Hh / 4) return;
    int c4 = i & 31;
    float4 gg = g2[c4], bb = b2[c4];
    float4 ou = ((const float4*)g_out)[i];
    float4 ml = ((const float4*)g_mlp)[i];
    float4 hh = ((const float4*)g_h)[i];
    float4 r;
    r.x = fmaxf((ou.x + ml.x) * bn_scale(gg.x) + bb.x + hh.x, 0.0f);
    r.y = fmaxf((ou.y + ml.y) * bn_scale(gg.y) + bb.y + hh.y, 0.0f);
    r.z = fmaxf((ou.z + ml.z) * bn_scale(gg.z) + bb.z + hh.z, 0.0f);
    r.w = fmaxf((ou.w + ml.w) * bn_scale(gg.w) + bb.w + hh.w, 0.0f);
    ((float4*)g_h)[i] = r;
}

// ---------------- host launch ----------------
extern "C" void kernel_launch(void* const* d_in, const int* in_sizes, int n_in,
                              void* d_out, int out_size) {
    const float* x       = (const float*)d_in[0];
    const int*   ei      = (const int*)d_in[1];
    const float* w_in    = (const float*)d_in[2];
    const float* b_in    = (const float*)d_in[3];
    const float* w_gat   = (const float*)d_in[4];
    const float* att_src = (const float*)d_in[5];
    const float* att_dst = (const float*)d_in[6];
    const float* b_gat   = (const float*)d_in[7];
    const float* w_qkv   = (const float*)d_in[8];
    const float* b_qkv   = (const float*)d_in[9];
    const float* w_o     = (const float*)d_in[10];
    const float* b_o     = (const float*)d_in[11];
    const float* bn_g    = (const float*)d_in[12];
    const float* bn_b    = (const float*)d_in[13];
    const float* w1      = (const float*)d_in[14];
    const float* b1      = (const float*)d_in[15];
    const float* w2      = (const float*)d_in[16];
    const float* b2      = (const float*)d_in[17];
    const float* w_out   = (const float*)d_in[18];
    const float* b_out   = (const float*)d_in[19];
    float* out = (float*)d_out;

    float *p_h, *p_xp, *p_qkv, *p_attn, *p_tmp, *p_out, *p_t1, *p_mlp;
    int* p_cnt;
    cudaGetSymbolAddress((void**)&p_h,    g_h);
    cudaGetSymbolAddress((void**)&p_xp,   g_xp);
    cudaGetSymbolAddress((void**)&p_qkv,  g_qkv);
    cudaGetSymbolAddress((void**)&p_attn, g_attn);
    cudaGetSymbolAddress((void**)&p_tmp,  g_tmp);
    cudaGetSymbolAddress((void**)&p_out,  g_out);
    cudaGetSymbolAddress((void**)&p_t1,   g_t1);
    cudaGetSymbolAddress((void**)&p_mlp,  g_mlp);
    cudaGetSymbolAddress((void**)&p_cnt,  g_cnt);

    dim3 gblk(16, 16);
    const int EW4 = (Nn * Hh / 4 + 255) / 256;

    // CSR build (per-launch, layer-independent)
    cudaMemsetAsync(p_cnt, 0, Nn * sizeof(int));
    csr_hist<<<(Ee + 255) / 256, 256>>>(ei);
    csr_scan<<<1, 1024>>>();
    csr_scatter<<<(Ee + 255) / 256, 256>>>(ei);

    // input projection: h = relu(x @ w_in^T + b_in)
    gemm_nt<<<dim3(2, 64), gblk>>>(x, w_in, b_in, p_h, Hh,
                                   nullptr, nullptr, nullptr, 0, Nn, IND, 1);

    for (int l = 0; l < Ll; l++) {
        // ---- fused GAT projection + QKV projection (one launch, 512 blocks) ----
        gemm_nt<<<dim3(8, 64), gblk>>>(p_h,
                                       w_gat + l * Hh * Hh, nullptr, p_xp, Hh,
                                       w_qkv + l * 3 * Hh * Hh, b_qkv + l * 3 * Hh, p_qkv, 3 * Hh,
                                       Nn, Hh, 0);
        // ---- GAT branch ----
        att_logits<<<(Nn * NHEADS + 127) / 128, 128>>>(att_src + l * Hh, att_dst + l * Hh);
        gat_fused<<<Nn, 128>>>(b_gat + l * Hh, bn_g + (l * 3 + 0) * Hh, bn_b + (l * 3 + 0) * Hh);

        // ---- global attention branch ----
        flash_attn<<<dim3(Nn / 64, NHEADS, KSPLIT), 64>>>();
        flash_merge<<<(NQH * DHd + 255) / 256, 256>>>();
        gemm_nt<<<dim3(2, 64), gblk>>>(p_attn, w_o + l * Hh * Hh, b_o + l * Hh, p_tmp, Hh,
                                       nullptr, nullptr, nullptr, 0, Nn, Hh, 0);
        combine_att<<<EW4, 256>>>((const float4*)(bn_g + (l * 3 + 1) * Hh),
                                  (const float4*)(bn_b + (l * 3 + 1) * Hh));

        // ---- MLP ----
        gemm_nt<<<dim3(4, 64), gblk>>>(p_out, w1 + l * 2 * Hh * Hh, b1 + l * 2 * Hh, p_t1, 2 * Hh,
                                       nullptr, nullptr, nullptr, 0, Nn, Hh, 1);
        gemm_nt<<<dim3(2, 64), gblk>>>(p_t1, w2 + l * 2 * Hh * Hh, b2 + l * Hh, p_mlp, Hh,
                                       nullptr, nullptr, nullptr, 0, Nn, 2 * Hh, 0);
        final_combine<<<EW4, 256>>>((const float4*)(bn_g + (l * 3 + 2) * Hh),
                                    (const float4*)(bn_b + (l * 3 + 2) * Hh));
    }

    // output projection -> [4096, 2]
    gemm_nt<<<dim3(1, 64), gblk>>>(p_h, w_out, b_out, out, 2,
                                   nullptr, nullptr, nullptr, 0, Nn, Hh, 0);
}

// round 4
// speedup vs baseline: 2.7543x; 1.1537x over previous
#include <cuda_runtime.h>
#include <math.h>

#define Nn 4096
#define Ee 262144
#define IND 64
#define Hh 128
#define NHEADS 4
#define DHd 32
#define Ll 2
#define KSPLIT 8
#define NQH (Nn * NHEADS)
#define GATBLK Nn
#define FLASHBLK ((Nn / 128) * NHEADS * KSPLIT)   // 32*4*8 = 1024

typedef unsigned long long ull;

// ---------------- scratch (static device globals; no allocation) -------------
__device__ float g_h[Nn*Hh];
__device__ float g_xp[Nn*Hh];
__device__ float g_als[Nn*NHEADS];
__device__ float g_ald[Nn*NHEADS];
__device__ float g_hloc[Nn*Hh];
__device__ float g_qkv[Nn*3*Hh];
__device__ float g_attn[Nn*Hh];
__device__ float g_out[Nn*Hh];
__device__ float g_t1[Nn*2*Hh];
// flash split-K partials
__device__ float g_pm[KSPLIT*NQH];
__device__ float g_pl[KSPLIT*NQH];
__device__ float g_pacc[KSPLIT*NQH*DHd];
// CSR
__device__ int g_cnt[Nn];
__device__ int g_cursor[Nn];
__device__ int g_rowptr[Nn+1];
__device__ int g_srcs[Ee];

__device__ __forceinline__ float bn_scale(float g) { return g * rsqrtf(1.0f + 1e-5f); }

// ---- f32x2 packed helpers (sm_103a) ----
__device__ __forceinline__ ull pk(float a, float b) {
    ull r; asm("mov.b64 %0,{%1,%2};" : "=l"(r) : "f"(a), "f"(b)); return r;
}
__device__ __forceinline__ void upk(ull v, float& a, float& b) {
    asm("mov.b64 {%0,%1},%2;" : "=f"(a), "=f"(b) : "l"(v));
}
__device__ __forceinline__ ull f2fma(ull a, ull b, ull c) {
    ull d; asm("fma.rn.f32x2 %0,%1,%2,%3;" : "=l"(d) : "l"(a), "l"(b), "l"(c)); return d;
}
__device__ __forceinline__ ull f2mul(ull a, ull b) {
    ull d; asm("mul.rn.f32x2 %0,%1,%2;" : "=l"(d) : "l"(a), "l"(b)); return d;
}
__device__ __forceinline__ void cpa16(void* sdst, const void* gsrc) {
    unsigned s = (unsigned)__cvta_generic_to_shared(sdst);
    asm volatile("cp.async.cg.shared.global [%0],[%1],16;" :: "r"(s), "l"(gsrc));
}

// ---------------- GEMM with fused epilogues ----------------------------------
// mode 0: none   1: relu
// mode 2: C1[r,c] = epA[r,c] + (acc+bias + epH[r,c]) * bn_scale(epG[c]) + epB[c]
// mode 3: C1[r,c] = max( (epA[r,c] + acc+bias) * bn_scale(epG[c]) + epB[c] + epH[r,c], 0 )
__global__ void gemm_nt(const float* __restrict__ A,
                        const float* __restrict__ B1, const float* __restrict__ bias1,
                        float* __restrict__ C1, int M1,
                        const float* __restrict__ B2, const float* __restrict__ bias2,
                        float* __restrict__ C2, int M2,
                        int Nr, int K, int mode,
                        const float* __restrict__ epA, const float* __restrict__ epH,
                        const float* __restrict__ epG, const float* __restrict__ epB) {
    __shared__ float As[16][66];
    __shared__ ull   Bs[16][66];   // duplicated pairs (b,b)
    const int tx = threadIdx.x, ty = threadIdx.y;
    const int tid = ty * 16 + tx;
    const int r0 = blockIdx.y * 64;
    const int c0 = blockIdx.x * 64;
    const int Mtot = M1 + M2;
    ull acc[2][4];
    #pragma unroll
    for (int i = 0; i < 2; i++)
        #pragma unroll
        for (int j = 0; j < 4; j++) acc[i][j] = 0ull;

    for (int kt = 0; kt < K; kt += 16) {
        #pragma unroll
        for (int i = 0; i < 4; i++) {
            int idx = tid + i * 256;
            int kk = idx & 15;
            int rr = idx >> 4;
            As[kk][rr] = A[(r0 + rr) * K + kt + kk];
            int cc = c0 + rr;
            float bv = 0.0f;
            if (cc < Mtot) {
                const float* Brow = (cc < M1) ? (B1 + (size_t)cc * K)
                                              : (B2 + (size_t)(cc - M1) * K);
                bv = Brow[kt + kk];
            }
            Bs[kk][rr] = pk(bv, bv);
        }
        __syncthreads();
        #pragma unroll
        for (int kk = 0; kk < 16; kk++) {
            ull a01 = *(const ull*)&As[kk][ty * 4];
            ull a23 = *(const ull*)&As[kk][ty * 4 + 2];
            #pragma unroll
            for (int j = 0; j < 4; j++) {
                ull b = Bs[kk][tx + 16 * j];
                acc[0][j] = f2fma(a01, b, acc[0][j]);
                acc[1][j] = f2fma(a23, b, acc[1][j]);
            }
        }
        __syncthreads();
    }
    #pragma unroll
    for (int j = 0; j < 4; j++) {
        int c = c0 + tx + 16 * j;
        if (c >= Mtot) continue;
        float bsv;
        float* Cp;
        int ld;
        int cc;
        if (c < M1) { bsv = bias1 ? bias1[c] : 0.0f; Cp = C1; ld = M1; cc = c; }
        else        { bsv = bias2 ? bias2[c - M1] : 0.0f; Cp = C2; ld = M2; cc = c - M1; }
        float v[4];
        upk(acc[0][j], v[0], v[1]);
        upk(acc[1][j], v[2], v[3]);
        int rb = r0 + ty * 4;
        float gs = 0.0f, gb = 0.0f;
        if (mode >= 2) { gs = bn_scale(epG[c]); gb = epB[c]; }
        #pragma unroll
        for (int i = 0; i < 4; i++) {
            int r = rb + i;
            float val = v[i] + bsv;
            if (mode == 1) val = fmaxf(val, 0.0f);
            else if (mode == 2) val = epA[(size_t)r*ld+cc] + (val + epH[(size_t)r*ld+cc]) * gs + gb;
            else if (mode == 3) val = fmaxf((epA[(size_t)r*ld+cc] + val) * gs + gb + epH[(size_t)r*ld+cc], 0.0f);
            Cp[(size_t)r * ld + cc] = val;
        }
    }
}

// ---------------- CSR build ----------------
__global__ void csr_hist(const int* __restrict__ ei) {
    int e = blockIdx.x * blockDim.x + threadIdx.x;
    if (e < Ee) atomicAdd(&g_cnt[ei[Ee + e]], 1);
}

__global__ void csr_scan() {   // one block, 1024 threads, 4 elems each
    __shared__ int sm[1024];
    int t = threadIdx.x;
    int b = t * 4;
    int c0 = g_cnt[b], c1 = g_cnt[b+1], c2 = g_cnt[b+2], c3 = g_cnt[b+3];
    int s1 = c0 + c1, s2 = s1 + c2, s3 = s2 + c3;
    sm[t] = s3;
    __syncthreads();
    for (int off = 1; off < 1024; off <<= 1) {
        int v = (t >= off) ? sm[t - off] : 0;
        __syncthreads();
        sm[t] += v;
        __syncthreads();
    }
    int excl = sm[t] - s3;
    g_rowptr[b]   = excl;
    g_rowptr[b+1] = excl + c0;
    g_rowptr[b+2] = excl + s1;
    g_rowptr[b+3] = excl + s2;
    g_cursor[b]   = excl;
    g_cursor[b+1] = excl + c0;
    g_cursor[b+2] = excl + s1;
    g_cursor[b+3] = excl + s2;
    if (t == 1023) g_rowptr[Nn] = sm[1023];
}

__global__ void csr_scatter(const int* __restrict__ ei) {
    int e = blockIdx.x * blockDim.x + threadIdx.x;
    if (e >= Ee) return;
    int d = ei[Ee + e];
    int pos = atomicAdd(&g_cursor[d], 1);
    g_srcs[pos] = ei[e];
}

// ---------------- GAT: per-node attention logits ----------------
__global__ void att_logits(const float* __restrict__ asrc, const float* __restrict__ adst) {
    int i = blockIdx.x * blockDim.x + threadIdx.x;
    if (i >= Nn * NHEADS) return;
    int n = i >> 2, hd = i & 3;
    const float4* xp = (const float4*)&g_xp[n * Hh + hd * DHd];
    const float4* as = (const float4*)&asrc[hd * DHd];
    const float4* ad = (const float4*)&adst[hd * DHd];
    float s = 0.0f, t = 0.0f;
    #pragma unroll
    for (int d4 = 0; d4 < 8; d4++) {
        float4 v = xp[d4], a = as[d4], b = ad[d4];
        s += v.x*a.x + v.y*a.y + v.z*a.z + v.w*a.w;
        t += v.x*b.x + v.y*b.y + v.z*b.z + v.w*b.w;
    }
    g_als[i] = s;
    g_ald[i] = t;
}

__device__ __forceinline__ float leaky(float x) { return x >= 0.0f ? x : 0.2f * x; }

// ---------------- FAT kernel: blocks [0,4096) = GAT, [4096,5120) = flash -----
__global__ void __launch_bounds__(128, 5) gat_flash(
        const float* __restrict__ bias, const float* __restrict__ g0,
        const float* __restrict__ b0) {
    __shared__ int    s_src[128];
    __shared__ float  s_w[128][4];
    __shared__ float4 s_red[128];
    __shared__ ulonglong2 Ks[2][32][8];
    __shared__ ulonglong2 Vs[2][32][8];
    const int t = threadIdx.x;

    if (blockIdx.x < GATBLK) {
        // =========== GAT aggregation for dst node d ===========
        const int d = blockIdx.x;
        const int head = t >> 5;
        const int beg = g_rowptr[d], end = g_rowptr[d + 1];
        const float4 ad4 = *(const float4*)&g_ald[d * 4];

        const float NEGINF = -__int_as_float(0x7f800000);
        float4 mx = make_float4(NEGINF, NEGINF, NEGINF, NEGINF);
        for (int e = beg + t; e < end; e += 128) {
            int s = g_srcs[e];
            float4 as = *(const float4*)&g_als[s * 4];
            mx.x = fmaxf(mx.x, leaky(as.x + ad4.x));
            mx.y = fmaxf(mx.y, leaky(as.y + ad4.y));
            mx.z = fmaxf(mx.z, leaky(as.z + ad4.z));
            mx.w = fmaxf(mx.w, leaky(as.w + ad4.w));
        }
        s_red[t] = mx;
        __syncthreads();
        for (int off = 64; off > 0; off >>= 1) {
            if (t < off) {
                float4 a = s_red[t], b = s_red[t + off];
                s_red[t] = make_float4(fmaxf(a.x,b.x), fmaxf(a.y,b.y), fmaxf(a.z,b.z), fmaxf(a.w,b.w));
            }
            __syncthreads();
        }
        const float4 m4 = s_red[0];
        __syncthreads();

        float4 den = make_float4(0,0,0,0);
        float acc = 0.0f;
        for (int cb = beg; cb < end; cb += 128) {
            int cnt = min(128, end - cb);
            if (t < cnt) {
                int s = g_srcs[cb + t];
                s_src[t] = s;
                float4 as = *(const float4*)&g_als[s * 4];
                float w0 = __expf(leaky(as.x + ad4.x) - m4.x);
                float w1 = __expf(leaky(as.y + ad4.y) - m4.y);
                float w2 = __expf(leaky(as.z + ad4.z) - m4.z);
                float w3 = __expf(leaky(as.w + ad4.w) - m4.w);
                s_w[t][0] = w0; s_w[t][1] = w1; s_w[t][2] = w2; s_w[t][3] = w3;
                den.x += w0; den.y += w1; den.z += w2; den.w += w3;
            }
            __syncthreads();
            #pragma unroll 4
            for (int i = 0; i < cnt; i++)
                acc = fmaf(s_w[i][head], g_xp[s_src[i] * Hh + t], acc);
            __syncthreads();
        }
        s_red[t] = den;
        __syncthreads();
        for (int off = 64; off > 0; off >>= 1) {
            if (t < off) {
                float4 a = s_red[t], b = s_red[t + off];
                s_red[t] = make_float4(a.x+b.x, a.y+b.y, a.z+b.z, a.w+b.w);
            }
            __syncthreads();
        }
        float4 den4 = s_red[0];
        float denh = head == 0 ? den4.x : head == 1 ? den4.y : head == 2 ? den4.z : den4.w;
        float v = acc / (denh + 1e-16f) + bias[t] + g_h[d * Hh + t];
        g_hloc[d * Hh + t] = v * bn_scale(g0[t]) + b0[t];
    } else {
        // =========== flash attention split-K ===========
        const int fb = blockIdx.x - GATBLK;
        const int qb = fb & 31;
        const int hd = (fb >> 5) & 3;
        const int sp = fb >> 7;
        const int n = qb * 128 + t;
        const int kbase = sp * (Nn / KSPLIT);   // 512 keys per split
        const int kend  = kbase + Nn / KSPLIT;

        ull q2[16];
        {
            const float sc = 0.17677669529663687f;   // 1/sqrt(32)
            ull scp = pk(sc, sc);
            const ulonglong2* qp = (const ulonglong2*)&g_qkv[n * 384 + hd * DHd];
            #pragma unroll
            for (int i = 0; i < 8; i++) {
                ulonglong2 v = qp[i];
                q2[2*i]   = f2mul(v.x, scp);
                q2[2*i+1] = f2mul(v.y, scp);
            }
        }

        auto load_tile = [&](int kb, int buf) {
            #pragma unroll
            for (int idx = t; idx < 256; idx += 128) {
                int j = idx >> 3, d4 = idx & 7;
                const float* kp = &g_qkv[(kb + j) * 384 + 128 + hd * DHd + d4 * 4];
                cpa16(&Ks[buf][j][d4], kp);
                cpa16(&Vs[buf][j][d4], kp + 128);
            }
            asm volatile("cp.async.commit_group;");
        };

        load_tile(kbase, 0);
        float mx = -__int_as_float(0x7f800000);
        float lsum = 0.0f;
        ull acc2[16];
        #pragma unroll
        for (int i = 0; i < 16; i++) acc2[i] = 0ull;

        for (int kb = kbase; kb < kend; kb += 32) {
            int buf = ((kb - kbase) >> 5) & 1;
            bool more = (kb + 32 < kend);
            if (more) load_tile(kb + 32, buf ^ 1);
            if (more) asm volatile("cp.async.wait_group 1;");
            else      asm volatile("cp.async.wait_group 0;");
            __syncthreads();

            #pragma unroll 2
            for (int j = 0; j < 32; j++) {
                ull s2a = 0ull, s2b = 0ull;
                #pragma unroll
                for (int d4 = 0; d4 < 8; d4++) {
                    ulonglong2 kk = Ks[buf][j][d4];
                    s2a = f2fma(q2[2*d4],   kk.x, s2a);
                    s2b = f2fma(q2[2*d4+1], kk.y, s2b);
                }
                float a0, a1, b0v, b1v;
                upk(s2a, a0, a1); upk(s2b, b0v, b1v);
                float s = (a0 + a1) + (b0v + b1v);
                if (s > mx) {
                    float c = __expf(mx - s);
                    lsum *= c;
                    ull c2 = pk(c, c);
                    #pragma unroll
                    for (int i = 0; i < 16; i++) acc2[i] = f2mul(acc2[i], c2);
                    mx = s;
                }
                float p = __expf(s - mx);
                lsum += p;
                ull p2 = pk(p, p);
                #pragma unroll
                for (int d4 = 0; d4 < 8; d4++) {
                    ulonglong2 vv = Vs[buf][j][d4];
                    acc2[2*d4]   = f2fma(p2, vv.x, acc2[2*d4]);
                    acc2[2*d4+1] = f2fma(p2, vv.y, acc2[2*d4+1]);
                }
            }
            __syncthreads();
        }

        const int qh = n * NHEADS + hd;
        g_pm[sp * NQH + qh] = mx;
        g_pl[sp * NQH + qh] = lsum;
        ulonglong2* op = (ulonglong2*)&g_pacc[((size_t)sp * NQH + qh) * DHd];
        #pragma unroll
        for (int i = 0; i < 8; i++) {
            ulonglong2 o;
            o.x = acc2[2*i];
            o.y = acc2[2*i+1];
            op[i] = o;
        }
    }
}

// merge split-K partials: thread per (qh, d)
__global__ void flash_merge() {
    int i = blockIdx.x * blockDim.x + threadIdx.x;
    if (i >= NQH * DHd) return;
    int qh = i >> 5;
    int d = i & 31;
    float ms[KSPLIT];
    float M = -__int_as_float(0x7f800000);
    #pragma unroll
    for (int s = 0; s < KSPLIT; s++) { ms[s] = g_pm[s*NQH+qh]; M = fmaxf(M, ms[s]); }
    float L = 0.0f, a = 0.0f;
    #pragma unroll
    for (int s = 0; s < KSPLIT; s++) {
        float w = __expf(ms[s] - M);
        L += g_pl[s*NQH+qh] * w;
        a += g_pacc[((size_t)s*NQH+qh)*DHd + d] * w;
    }
    int n = qh >> 2, hd = qh & 3;
    g_attn[n * Hh + hd * DHd + d] = a / L;
}

// ---------------- host launch ----------------
extern "C" void kernel_launch(void* const* d_in, const int* in_sizes, int n_in,
                              void* d_out, int out_size) {
    const float* x       = (const float*)d_in[0];
    const int*   ei      = (const int*)d_in[1];
    const float* w_in    = (const float*)d_in[2];
    const float* b_in    = (const float*)d_in[3];
    const float* w_gat   = (const float*)d_in[4];
    const float* att_src = (const float*)d_in[5];
    const float* att_dst = (const float*)d_in[6];
    const float* b_gat   = (const float*)d_in[7];
    const float* w_qkv   = (const float*)d_in[8];
    const float* b_qkv   = (const float*)d_in[9];
    const float* w_o     = (const float*)d_in[10];
    const float* b_o     = (const float*)d_in[11];
    const float* bn_g    = (const float*)d_in[12];
    const float* bn_b    = (const float*)d_in[13];
    const float* w1      = (const float*)d_in[14];
    const float* b1      = (const float*)d_in[15];
    const float* w2      = (const float*)d_in[16];
    const float* b2      = (const float*)d_in[17];
    const float* w_out   = (const float*)d_in[18];
    const float* b_out   = (const float*)d_in[19];
    float* out = (float*)d_out;

    float *p_h, *p_xp, *p_qkv, *p_attn, *p_out, *p_t1, *p_hloc;
    int* p_cnt;
    cudaGetSymbolAddress((void**)&p_h,    g_h);
    cudaGetSymbolAddress((void**)&p_xp,   g_xp);
    cudaGetSymbolAddress((void**)&p_qkv,  g_qkv);
    cudaGetSymbolAddress((void**)&p_attn, g_attn);
    cudaGetSymbolAddress((void**)&p_out,  g_out);
    cudaGetSymbolAddress((void**)&p_t1,   g_t1);
    cudaGetSymbolAddress((void**)&p_hloc, g_hloc);
    cudaGetSymbolAddress((void**)&p_cnt,  g_cnt);

    dim3 gblk(16, 16);

    // CSR build
    cudaMemsetAsync(p_cnt, 0, Nn * sizeof(int));
    csr_hist<<<(Ee + 255) / 256, 256>>>(ei);
    csr_scan<<<1, 1024>>>();
    csr_scatter<<<(Ee + 255) / 256, 256>>>(ei);

    // input projection: h = relu(x @ w_in^T + b_in)
    gemm_nt<<<dim3(2, 64), gblk>>>(x, w_in, b_in, p_h, Hh,
                                   nullptr, nullptr, nullptr, 0, Nn, IND, 1,
                                   nullptr, nullptr, nullptr, nullptr);

    for (int l = 0; l < Ll; l++) {
        // fused GAT projection + QKV projection
        gemm_nt<<<dim3(8, 64), gblk>>>(p_h,
                                       w_gat + l * Hh * Hh, nullptr, p_xp, Hh,
                                       w_qkv + l * 3 * Hh * Hh, b_qkv + l * 3 * Hh, p_qkv, 3 * Hh,
                                       Nn, Hh, 0, nullptr, nullptr, nullptr, nullptr);
        att_logits<<<(Nn * NHEADS + 127) / 128, 128>>>(att_src + l * Hh, att_dst + l * Hh);

        // FAT kernel: GAT aggregation (4096 blocks) + flash attention (1024 blocks)
        gat_flash<<<GATBLK + FLASHBLK, 128>>>(b_gat + l * Hh,
                                              bn_g + (l * 3 + 0) * Hh, bn_b + (l * 3 + 0) * Hh);
        flash_merge<<<(NQH * DHd + 255) / 256, 256>>>();

        // w_o GEMM with fused combine_att epilogue -> g_out
        gemm_nt<<<dim3(2, 64), gblk>>>(p_attn, w_o + l * Hh * Hh, b_o + l * Hh, p_out, Hh,
                                       nullptr, nullptr, nullptr, 0, Nn, Hh, 2,
                                       p_hloc, p_h,
                                       bn_g + (l * 3 + 1) * Hh, bn_b + (l * 3 + 1) * Hh);

        // MLP
        gemm_nt<<<dim3(4, 64), gblk>>>(p_out, w1 + l * 2 * Hh * Hh, b1 + l * 2 * Hh, p_t1, 2 * Hh,
                                       nullptr, nullptr, nullptr, 0, Nn, Hh, 1,
                                       nullptr, nullptr, nullptr, nullptr);
        // w2 GEMM with fused final_combine epilogue -> g_h
        gemm_nt<<<dim3(2, 64), gblk>>>(p_t1, w2 + l * 2 * Hh * Hh, b2 + l * Hh, p_h, Hh,
                                       nullptr, nullptr, nullptr, 0, Nn, 2 * Hh, 3,
                                       p_out, p_h,
                                       bn_g + (l * 3 + 2) * Hh, bn_b + (l * 3 + 2) * Hh);
    }

    // output projection -> [4096, 2]
    gemm_nt<<<dim3(1, 64), gblk>>>(p_h, w_out, b_out, out, 2,
                                   nullptr, nullptr, nullptr, 0, Nn, Hh, 0,
                                   nullptr, nullptr, nullptr, nullptr);
}

// round 5
// speedup vs baseline: 5.0542x; 1.8351x over previous
#include <cuda_runtime.h>
#include <math.h>

#define Nn 4096
#define Ee 262144
#define IND 64
#define Hh 128
#define NHEADS 4
#define DHd 32
#define Ll 2
#define KSPLIT 4
#define NQH (Nn * NHEADS)
#define FLASHBLK ((Nn / 64) * NHEADS * KSPLIT)   // 64*4*4 = 1024
#define NTILES ((Nn / KSPLIT) / 64)              // 16

typedef unsigned long long ull;

// ---------------- scratch (static device globals; no allocation) -------------
__device__ float g_h[Nn*Hh];
__device__ float g_xp[Nn*Hh];
__device__ float g_als[Nn*NHEADS];
__device__ float g_ald[Nn*NHEADS];
__device__ float g_hloc[Nn*Hh];
__device__ float g_qkv[Nn*3*Hh];
__device__ float g_attn[Nn*Hh];
__device__ float g_out[Nn*Hh];
__device__ float g_t1[Nn*2*Hh];
// flash split-K partials
__device__ float g_pm[KSPLIT*NQH];
__device__ float g_pl[KSPLIT*NQH];
__device__ float g_pacc[KSPLIT*NQH*DHd];
// CSR
__device__ int g_cnt[Nn];
__device__ int g_cursor[Nn];
__device__ int g_rowptr[Nn+1];
__device__ int g_srcs[Ee];

__device__ __forceinline__ float bn_scale(float g) { return g * rsqrtf(1.0f + 1e-5f); }

// ---- f32x2 packed helpers (sm_103a) ----
__device__ __forceinline__ ull pk(float a, float b) {
    ull r; asm("mov.b64 %0,{%1,%2};" : "=l"(r) : "f"(a), "f"(b)); return r;
}
__device__ __forceinline__ void upk(ull v, float& a, float& b) {
    asm("mov.b64 {%0,%1},%2;" : "=f"(a), "=f"(b) : "l"(v));
}
__device__ __forceinline__ ull f2fma(ull a, ull b, ull c) {
    ull d; asm("fma.rn.f32x2 %0,%1,%2,%3;" : "=l"(d) : "l"(a), "l"(b), "l"(c)); return d;
}

// ---- tf32 helpers ----
__device__ __forceinline__ unsigned tf32u(float f) {
    unsigned r; asm("cvt.rna.tf32.f32 %0,%1;" : "=r"(r) : "f"(f)); return r;
}
__device__ __forceinline__ float tf32f(float f) {
    return __uint_as_float(tf32u(f));
}
// D += A(m16k8,tf32) * B(k8n8,tf32)  ; C==D in-place
__device__ __forceinline__ void mma_tf32(float* d, const unsigned* a, unsigned b0, unsigned b1) {
    asm volatile(
        "mma.sync.aligned.m16n8k8.row.col.f32.tf32.tf32.f32 "
        "{%0,%1,%2,%3},{%4,%5,%6,%7},{%8,%9},{%0,%1,%2,%3};"
        : "+f"(d[0]), "+f"(d[1]), "+f"(d[2]), "+f"(d[3])
        : "r"(a[0]), "r"(a[1]), "r"(a[2]), "r"(a[3]), "r"(b0), "r"(b1));
}

// ---------------- GEMM with fused epilogues ----------------------------------
// mode 0: none   1: relu
// mode 2: C1[r,c] = epA[r,c] + (acc+bias + epH[r,c]) * bn_scale(epG[c]) + epB[c]
// mode 3: C1[r,c] = max( (epA[r,c] + acc+bias) * bn_scale(epG[c]) + epB[c] + epH[r,c], 0 )
__global__ void gemm_nt(const float* __restrict__ A,
                        const float* __restrict__ B1, const float* __restrict__ bias1,
                        float* __restrict__ C1, int M1,
                        const float* __restrict__ B2, const float* __restrict__ bias2,
                        float* __restrict__ C2, int M2,
                        int Nr, int K, int mode,
                        const float* __restrict__ epA, const float* __restrict__ epH,
                        const float* __restrict__ epG, const float* __restrict__ epB) {
    __shared__ float As[16][66];
    __shared__ ull   Bs[16][66];
    const int tx = threadIdx.x, ty = threadIdx.y;
    const int tid = ty * 16 + tx;
    const int r0 = blockIdx.y * 64;
    const int c0 = blockIdx.x * 64;
    const int Mtot = M1 + M2;
    ull acc[2][4];
    #pragma unroll
    for (int i = 0; i < 2; i++)
        #pragma unroll
        for (int j = 0; j < 4; j++) acc[i][j] = 0ull;

    for (int kt = 0; kt < K; kt += 16) {
        #pragma unroll
        for (int i = 0; i < 4; i++) {
            int idx = tid + i * 256;
            int kk = idx & 15;
            int rr = idx >> 4;
            As[kk][rr] = A[(r0 + rr) * K + kt + kk];
            int cc = c0 + rr;
            float bv = 0.0f;
            if (cc < Mtot) {
                const float* Brow = (cc < M1) ? (B1 + (size_t)cc * K)
                                              : (B2 + (size_t)(cc - M1) * K);
                bv = Brow[kt + kk];
            }
            Bs[kk][rr] = pk(bv, bv);
        }
        __syncthreads();
        #pragma unroll
        for (int kk = 0; kk < 16; kk++) {
            ull a01 = *(const ull*)&As[kk][ty * 4];
            ull a23 = *(const ull*)&As[kk][ty * 4 + 2];
            #pragma unroll
            for (int j = 0; j < 4; j++) {
                ull b = Bs[kk][tx + 16 * j];
                acc[0][j] = f2fma(a01, b, acc[0][j]);
                acc[1][j] = f2fma(a23, b, acc[1][j]);
            }
        }
        __syncthreads();
    }
    #pragma unroll
    for (int j = 0; j < 4; j++) {
        int c = c0 + tx + 16 * j;
        if (c >= Mtot) continue;
        float bsv;
        float* Cp;
        int ld;
        int cc;
        if (c < M1) { bsv = bias1 ? bias1[c] : 0.0f; Cp = C1; ld = M1; cc = c; }
        else        { bsv = bias2 ? bias2[c - M1] : 0.0f; Cp = C2; ld = M2; cc = c - M1; }
        float v[4];
        upk(acc[0][j], v[0], v[1]);
        upk(acc[1][j], v[2], v[3]);
        int rb = r0 + ty * 4;
        float gs = 0.0f, gb = 0.0f;
        if (mode >= 2) { gs = bn_scale(epG[c]); gb = epB[c]; }
        #pragma unroll
        for (int i = 0; i < 4; i++) {
            int r = rb + i;
            float val = v[i] + bsv;
            if (mode == 1) val = fmaxf(val, 0.0f);
            else if (mode == 2) val = epA[(size_t)r*ld+cc] + (val + epH[(size_t)r*ld+cc]) * gs + gb;
            else if (mode == 3) val = fmaxf((epA[(size_t)r*ld+cc] + val) * gs + gb + epH[(size_t)r*ld+cc], 0.0f);
            Cp[(size_t)r * ld + cc] = val;
        }
    }
}

// ---------------- CSR build ----------------
__global__ void csr_hist(const int* __restrict__ ei) {
    int e = blockIdx.x * blockDim.x + threadIdx.x;
    if (e < Ee) atomicAdd(&g_cnt[ei[Ee + e]], 1);
}

__global__ void csr_scan() {
    __shared__ int sm[1024];
    int t = threadIdx.x;
    int b = t * 4;
    int c0 = g_cnt[b], c1 = g_cnt[b+1], c2 = g_cnt[b+2], c3 = g_cnt[b+3];
    int s1 = c0 + c1, s2 = s1 + c2, s3 = s2 + c3;
    sm[t] = s3;
    __syncthreads();
    for (int off = 1; off < 1024; off <<= 1) {
        int v = (t >= off) ? sm[t - off] : 0;
        __syncthreads();
        sm[t] += v;
        __syncthreads();
    }
    int excl = sm[t] - s3;
    g_rowptr[b]   = excl;
    g_rowptr[b+1] = excl + c0;
    g_rowptr[b+2] = excl + s1;
    g_rowptr[b+3] = excl + s2;
    g_cursor[b]   = excl;
    g_cursor[b+1] = excl + c0;
    g_cursor[b+2] = excl + s1;
    g_cursor[b+3] = excl + s2;
    if (t == 1023) g_rowptr[Nn] = sm[1023];
}

__global__ void csr_scatter(const int* __restrict__ ei) {
    int e = blockIdx.x * blockDim.x + threadIdx.x;
    if (e >= Ee) return;
    int d = ei[Ee + e];
    int pos = atomicAdd(&g_cursor[d], 1);
    g_srcs[pos] = ei[e];
}

// ---------------- GAT: per-node attention logits ----------------
__global__ void att_logits(const float* __restrict__ asrc, const float* __restrict__ adst) {
    int i = blockIdx.x * blockDim.x + threadIdx.x;
    if (i >= Nn * NHEADS) return;
    int n = i >> 2, hd = i & 3;
    const float4* xp = (const float4*)&g_xp[n * Hh + hd * DHd];
    const float4* as = (const float4*)&asrc[hd * DHd];
    const float4* ad = (const float4*)&adst[hd * DHd];
    float s = 0.0f, t = 0.0f;
    #pragma unroll
    for (int d4 = 0; d4 < 8; d4++) {
        float4 v = xp[d4], a = as[d4], b = ad[d4];
        s += v.x*a.x + v.y*a.y + v.z*a.z + v.w*a.w;
        t += v.x*b.x + v.y*b.y + v.z*b.z + v.w*b.w;
    }
    g_als[i] = s;
    g_ald[i] = t;
}

__device__ __forceinline__ float leaky(float x) { return x >= 0.0f ? x : 0.2f * x; }

// shared-memory union for the fat kernel
union FatSmem {
    struct {
        int    s_src[128];
        float  s_w[128][4];
        float4 s_red[128];
    } gat;
    struct {
        float Ks[64][36];      // pad 36: fragment loads conflict-free
        float Vs[64][40];      // pad 40
        float Ps[4][16][68];   // pad 68: per-warp P staging
    } fl;
};

// ---------------- FAT kernel: blocks [0,1024) = flash, [1024,5120) = GAT -----
__global__ void __launch_bounds__(128) gat_flash(
        const float* __restrict__ bias, const float* __restrict__ g0,
        const float* __restrict__ b0) {
    __shared__ FatSmem sm;
    const int t = threadIdx.x;
    const float NEGINF = -__int_as_float(0x7f800000);

    if (blockIdx.x < FLASHBLK) {
        // =========== tensor-core flash attention (tf32 mma) ===========
        const int fb = blockIdx.x;
        const int qt = fb & 63;
        const int hd = (fb >> 6) & 3;
        const int sp = fb >> 8;
        const int w = t >> 5, lane = t & 31;
        const int gi = lane >> 2, li = lane & 3;
        const int q0 = qt * 64 + w * 16;
        const int kbase = sp * (Nn / KSPLIT);

        // Q fragments (scaled, tf32-rounded)
        unsigned qa[4][4];
        {
            const float scq = 0.17677669529663687f;   // 1/sqrt(32)
            #pragma unroll
            for (int ks = 0; ks < 4; ks++) {
                int c = hd * 32 + ks * 8 + li;
                qa[ks][0] = tf32u(g_qkv[(q0+gi  )*384 + c] * scq);
                qa[ks][1] = tf32u(g_qkv[(q0+gi+8)*384 + c] * scq);
                qa[ks][2] = tf32u(g_qkv[(q0+gi  )*384 + c+4] * scq);
                qa[ks][3] = tf32u(g_qkv[(q0+gi+8)*384 + c+4] * scq);
            }
        }

        float4 kst[4], vst[4];   // register staging for next tile
        auto ldg_tile = [&](int ti) {
            int kb = kbase + ti * 64;
            #pragma unroll
            for (int i = 0; i < 4; i++) {
                int c = t + i * 128;          // 0..511
                int j = c >> 3, d4 = c & 7;
                const float4* p = (const float4*)&g_qkv[(kb + j) * 384 + 128 + hd * 32 + d4 * 4];
                kst[i] = p[0];
                vst[i] = p[32];               // +128 floats
            }
        };
        auto sts_tile = [&]() {
            #pragma unroll
            for (int i = 0; i < 4; i++) {
                int c = t + i * 128;
                int j = c >> 3, d4 = c & 7;
                float4 k4 = kst[i], v4 = vst[i];
                k4.x = tf32f(k4.x); k4.y = tf32f(k4.y); k4.z = tf32f(k4.z); k4.w = tf32f(k4.w);
                v4.x = tf32f(v4.x); v4.y = tf32f(v4.y); v4.z = tf32f(v4.z); v4.w = tf32f(v4.w);
                *(float4*)&sm.fl.Ks[j][d4 * 4] = k4;
                *(float4*)&sm.fl.Vs[j][d4 * 4] = v4;
            }
        };

        float mxl = NEGINF, mxh = NEGINF, lsl = 0.0f, lsh = 0.0f;
        float o[4][4];
        #pragma unroll
        for (int jn = 0; jn < 4; jn++)
            #pragma unroll
            for (int i = 0; i < 4; i++) o[jn][i] = 0.0f;

        ldg_tile(0);
        for (int ti = 0; ti < NTILES; ti++) {
            __syncthreads();
            sts_tile();
            if (ti + 1 < NTILES) ldg_tile(ti + 1);
            __syncthreads();

            // S = Q @ K^T  (16 x 64 per warp)
            float s[8][4];
            #pragma unroll
            for (int jk = 0; jk < 8; jk++) {
                s[jk][0] = s[jk][1] = s[jk][2] = s[jk][3] = 0.0f;
                #pragma unroll
                for (int ks = 0; ks < 4; ks++) {
                    unsigned b0v = __float_as_uint(sm.fl.Ks[jk*8+gi][ks*8+li]);
                    unsigned b1v = __float_as_uint(sm.fl.Ks[jk*8+gi][ks*8+li+4]);
                    mma_tf32(s[jk], qa[ks], b0v, b1v);
                }
            }
            // tile row max
            float tml = NEGINF, tmh = NEGINF;
            #pragma unroll
            for (int jk = 0; jk < 8; jk++) {
                tml = fmaxf(tml, fmaxf(s[jk][0], s[jk][1]));
                tmh = fmaxf(tmh, fmaxf(s[jk][2], s[jk][3]));
            }
            tml = fmaxf(tml, __shfl_xor_sync(0xffffffffu, tml, 1));
            tml = fmaxf(tml, __shfl_xor_sync(0xffffffffu, tml, 2));
            tmh = fmaxf(tmh, __shfl_xor_sync(0xffffffffu, tmh, 1));
            tmh = fmaxf(tmh, __shfl_xor_sync(0xffffffffu, tmh, 2));
            float nml = fmaxf(mxl, tml), nmh = fmaxf(mxh, tmh);
            float scl = __expf(mxl - nml), sch = __expf(mxh - nmh);
            mxl = nml; mxh = nmh;
            lsl *= scl; lsh *= sch;
            #pragma unroll
            for (int jn = 0; jn < 4; jn++) {
                o[jn][0] *= scl; o[jn][1] *= scl;
                o[jn][2] *= sch; o[jn][3] *= sch;
            }
            // p = exp(s - m), row sums, stage P (tf32) to smem
            float rsl = 0.0f, rsh = 0.0f;
            #pragma unroll
            for (int jk = 0; jk < 8; jk++) {
                float p0 = __expf(s[jk][0] - mxl), p1 = __expf(s[jk][1] - mxl);
                float p2 = __expf(s[jk][2] - mxh), p3 = __expf(s[jk][3] - mxh);
                rsl += p0 + p1; rsh += p2 + p3;
                float2 lo = make_float2(tf32f(p0), tf32f(p1));
                float2 hi = make_float2(tf32f(p2), tf32f(p3));
                *(float2*)&sm.fl.Ps[w][gi  ][jk*8 + 2*li] = lo;
                *(float2*)&sm.fl.Ps[w][gi+8][jk*8 + 2*li] = hi;
            }
            rsl += __shfl_xor_sync(0xffffffffu, rsl, 1);
            rsl += __shfl_xor_sync(0xffffffffu, rsl, 2);
            rsh += __shfl_xor_sync(0xffffffffu, rsh, 1);
            rsh += __shfl_xor_sync(0xffffffffu, rsh, 2);
            lsl += rsl; lsh += rsh;
            __syncwarp();
            // O += P @ V
            #pragma unroll
            for (int kk = 0; kk < 8; kk++) {
                unsigned pa[4];
                pa[0] = __float_as_uint(sm.fl.Ps[w][gi  ][kk*8 + li]);
                pa[1] = __float_as_uint(sm.fl.Ps[w][gi+8][kk*8 + li]);
                pa[2] = __float_as_uint(sm.fl.Ps[w][gi  ][kk*8 + li + 4]);
                pa[3] = __float_as_uint(sm.fl.Ps[w][gi+8][kk*8 + li + 4]);
                #pragma unroll
                for (int jn = 0; jn < 4; jn++) {
                    unsigned b0v = __float_as_uint(sm.fl.Vs[kk*8+li  ][jn*8+gi]);
                    unsigned b1v = __float_as_uint(sm.fl.Vs[kk*8+li+4][jn*8+gi]);
                    mma_tf32(o[jn], pa, b0v, b1v);
                }
            }
            __syncwarp();
        }

        // write partials
        const int nl = q0 + gi, nh = nl + 8;
        const int qhl = nl * 4 + hd, qhh = nh * 4 + hd;
        if (li == 0) {
            g_pm[sp * NQH + qhl] = mxl;
            g_pl[sp * NQH + qhl] = lsl;
            g_pm[sp * NQH + qhh] = mxh;
            g_pl[sp * NQH + qhh] = lsh;
        }
        #pragma unroll
        for (int jn = 0; jn < 4; jn++) {
            int dh = jn * 8 + 2 * li;
            *(float2*)&g_pacc[((size_t)sp * NQH + qhl) * DHd + dh] = make_float2(o[jn][0], o[jn][1]);
            *(float2*)&g_pacc[((size_t)sp * NQH + qhh) * DHd + dh] = make_float2(o[jn][2], o[jn][3]);
        }
    } else {
        // =========== GAT aggregation for dst node d ===========
        const int d = blockIdx.x - FLASHBLK;
        const int head = t >> 5;
        const int beg = g_rowptr[d], end = g_rowptr[d + 1];
        const float4 ad4 = *(const float4*)&g_ald[d * 4];

        float4 mx = make_float4(NEGINF, NEGINF, NEGINF, NEGINF);
        for (int e = beg + t; e < end; e += 128) {
            int s = g_srcs[e];
            float4 as = *(const float4*)&g_als[s * 4];
            mx.x = fmaxf(mx.x, leaky(as.x + ad4.x));
            mx.y = fmaxf(mx.y, leaky(as.y + ad4.y));
            mx.z = fmaxf(mx.z, leaky(as.z + ad4.z));
            mx.w = fmaxf(mx.w, leaky(as.w + ad4.w));
        }
        sm.gat.s_red[t] = mx;
        __syncthreads();
        for (int off = 64; off > 0; off >>= 1) {
            if (t < off) {
                float4 a = sm.gat.s_red[t], b = sm.gat.s_red[t + off];
                sm.gat.s_red[t] = make_float4(fmaxf(a.x,b.x), fmaxf(a.y,b.y), fmaxf(a.z,b.z), fmaxf(a.w,b.w));
            }
            __syncthreads();
        }
        const float4 m4 = sm.gat.s_red[0];
        __syncthreads();

        float4 den = make_float4(0,0,0,0);
        float acc = 0.0f;
        for (int cb = beg; cb < end; cb += 128) {
            int cnt = min(128, end - cb);
            if (t < cnt) {
                int s = g_srcs[cb + t];
                sm.gat.s_src[t] = s;
                float4 as = *(const float4*)&g_als[s * 4];
                float w0 = __expf(leaky(as.x + ad4.x) - m4.x);
                float w1 = __expf(leaky(as.y + ad4.y) - m4.y);
                float w2 = __expf(leaky(as.z + ad4.z) - m4.z);
                float w3 = __expf(leaky(as.w + ad4.w) - m4.w);
                sm.gat.s_w[t][0] = w0; sm.gat.s_w[t][1] = w1;
                sm.gat.s_w[t][2] = w2; sm.gat.s_w[t][3] = w3;
                den.x += w0; den.y += w1; den.z += w2; den.w += w3;
            }
            __syncthreads();
            #pragma unroll 4
            for (int i = 0; i < cnt; i++)
                acc = fmaf(sm.gat.s_w[i][head], g_xp[sm.gat.s_src[i] * Hh + t], acc);
            __syncthreads();
        }
        sm.gat.s_red[t] = den;
        __syncthreads();
        for (int off = 64; off > 0; off >>= 1) {
            if (t < off) {
                float4 a = sm.gat.s_red[t], b = sm.gat.s_red[t + off];
                sm.gat.s_red[t] = make_float4(a.x+b.x, a.y+b.y, a.z+b.z, a.w+b.w);
            }
            __syncthreads();
        }
        float4 den4 = sm.gat.s_red[0];
        float denh = head == 0 ? den4.x : head == 1 ? den4.y : head == 2 ? den4.z : den4.w;
        float v = acc / (denh + 1e-16f) + bias[t] + g_h[d * Hh + t];
        g_hloc[d * Hh + t] = v * bn_scale(g0[t]) + b0[t];
    }
}

// merge split-K partials: thread per (qh, d)
__global__ void flash_merge() {
    int i = blockIdx.x * blockDim.x + threadIdx.x;
    if (i >= NQH * DHd) return;
    int qh = i >> 5;
    int d = i & 31;
    float ms[KSPLIT];
    float M = -__int_as_float(0x7f800000);
    #pragma unroll
    for (int s = 0; s < KSPLIT; s++) { ms[s] = g_pm[s*NQH+qh]; M = fmaxf(M, ms[s]); }
    float L = 0.0f, a = 0.0f;
    #pragma unroll
    for (int s = 0; s < KSPLIT; s++) {
        float w = __expf(ms[s] - M);
        L += g_pl[s*NQH+qh] * w;
        a += g_pacc[((size_t)s*NQH+qh)*DHd + d] * w;
    }
    int n = qh >> 2, hd = qh & 3;
    g_attn[n * Hh + hd * DHd + d] = a / L;
}

// ---------------- host launch ----------------
extern "C" void kernel_launch(void* const* d_in, const int* in_sizes, int n_in,
                              void* d_out, int out_size) {
    const float* x       = (const float*)d_in[0];
    const int*   ei      = (const int*)d_in[1];
    const float* w_in    = (const float*)d_in[2];
    const float* b_in    = (const float*)d_in[3];
    const float* w_gat   = (const float*)d_in[4];
    const float* att_src = (const float*)d_in[5];
    const float* att_dst = (const float*)d_in[6];
    const float* b_gat   = (const float*)d_in[7];
    const float* w_qkv   = (const float*)d_in[8];
    const float* b_qkv   = (const float*)d_in[9];
    const float* w_o     = (const float*)d_in[10];
    const float* b_o     = (const float*)d_in[11];
    const float* bn_g    = (const float*)d_in[12];
    const float* bn_b    = (const float*)d_in[13];
    const float* w1      = (const float*)d_in[14];
    const float* b1      = (const float*)d_in[15];
    const float* w2      = (const float*)d_in[16];
    const float* b2      = (const float*)d_in[17];
    const float* w_out   = (const float*)d_in[18];
    const float* b_out   = (const float*)d_in[19];
    float* out = (float*)d_out;

    float *p_h, *p_xp, *p_qkv, *p_attn, *p_out, *p_t1, *p_hloc;
    int* p_cnt;
    cudaGetSymbolAddress((void**)&p_h,    g_h);
    cudaGetSymbolAddress((void**)&p_xp,   g_xp);
    cudaGetSymbolAddress((void**)&p_qkv,  g_qkv);
    cudaGetSymbolAddress((void**)&p_attn, g_attn);
    cudaGetSymbolAddress((void**)&p_out,  g_out);
    cudaGetSymbolAddress((void**)&p_t1,   g_t1);
    cudaGetSymbolAddress((void**)&p_hloc, g_hloc);
    cudaGetSymbolAddress((void**)&p_cnt,  g_cnt);

    dim3 gblk(16, 16);

    // CSR build
    cudaMemsetAsync(p_cnt, 0, Nn * sizeof(int));
    csr_hist<<<(Ee + 255) / 256, 256>>>(ei);
    csr_scan<<<1, 1024>>>();
    csr_scatter<<<(Ee + 255) / 256, 256>>>(ei);

    // input projection: h = relu(x @ w_in^T + b_in)
    gemm_nt<<<dim3(2, 64), gblk>>>(x, w_in, b_in, p_h, Hh,
                                   nullptr, nullptr, nullptr, 0, Nn, IND, 1,
                                   nullptr, nullptr, nullptr, nullptr);

    for (int l = 0; l < Ll; l++) {
        // fused GAT projection + QKV projection
        gemm_nt<<<dim3(8, 64), gblk>>>(p_h,
                                       w_gat + l * Hh * Hh, nullptr, p_xp, Hh,
                                       w_qkv + l * 3 * Hh * Hh, b_qkv + l * 3 * Hh, p_qkv, 3 * Hh,
                                       Nn, Hh, 0, nullptr, nullptr, nullptr, nullptr);
        att_logits<<<(Nn * NHEADS + 127) / 128, 128>>>(att_src + l * Hh, att_dst + l * Hh);

        // FAT kernel: flash attention (1024 blocks, first) + GAT aggregation (4096 blocks)
        gat_flash<<<FLASHBLK + Nn, 128>>>(b_gat + l * Hh,
                                          bn_g + (l * 3 + 0) * Hh, bn_b + (l * 3 + 0) * Hh);
        flash_merge<<<(NQH * DHd + 255) / 256, 256>>>();

        // w_o GEMM with fused combine_att epilogue -> g_out
        gemm_nt<<<dim3(2, 64), gblk>>>(p_attn, w_o + l * Hh * Hh, b_o + l * Hh, p_out, Hh,
                                       nullptr, nullptr, nullptr, 0, Nn, Hh, 2,
                                       p_hloc, p_h,
                                       bn_g + (l * 3 + 1) * Hh, bn_b + (l * 3 + 1) * Hh);

        // MLP
        gemm_nt<<<dim3(4, 64), gblk>>>(p_out, w1 + l * 2 * Hh * Hh, b1 + l * 2 * Hh, p_t1, 2 * Hh,
                                       nullptr, nullptr, nullptr, 0, Nn, Hh, 1,
                                       nullptr, nullptr, nullptr, nullptr);
        // w2 GEMM with fused final_combine epilogue -> g_h
        gemm_nt<<<dim3(2, 64), gblk>>>(p_t1, w2 + l * 2 * Hh * Hh, b2 + l * Hh, p_h, Hh,
                                       nullptr, nullptr, nullptr, 0, Nn, 2 * Hh, 3,
                                       p_out, p_h,
                                       bn_g + (l * 3 + 2) * Hh, bn_b + (l * 3 + 2) * Hh);
    }

    // output projection -> [4096, 2]
    gemm_nt<<<dim3(1, 64), gblk>>>(p_h, w_out, b_out, out, 2,
                                   nullptr, nullptr, nullptr, 0, Nn, Hh, 0,
                                   nullptr, nullptr, nullptr, nullptr);
}

// round 6
// speedup vs baseline: 5.3794x; 1.0643x over previous
#include <cuda_runtime.h>
#include <math.h>

#define Nn 4096
#define Ee 262144
#define IND 64
#define Hh 128
#define NHEADS 4
#define DHd 32
#define Ll 2
#define KSPLIT 4
#define NQH (Nn * NHEADS)
#define FLASHBLK ((Nn / 64) * NHEADS * KSPLIT)   // 64*4*4 = 1024
#define NTILES ((Nn / KSPLIT) / 64)              // 16

typedef unsigned long long ull;

// ---------------- scratch (static device globals; no allocation) -------------
__device__ float g_h[Nn*Hh];
__device__ float g_xp[Nn*Hh];
__device__ float g_als[Nn*NHEADS];
__device__ float g_ald[Nn*NHEADS];
__device__ float g_hloc[Nn*Hh];
__device__ float g_qkv[Nn*3*Hh];
__device__ float g_attn[Nn*Hh];
__device__ float g_out[Nn*Hh];
__device__ float g_t1[Nn*2*Hh];
// flash split-K partials
__device__ float g_pm[KSPLIT*NQH];
__device__ float g_pl[KSPLIT*NQH];
__device__ float g_pacc[KSPLIT*NQH*DHd];
// CSR
__device__ int g_cnt[Nn];
__device__ int g_cursor[Nn];
__device__ int g_rowptr[Nn+1];
__device__ int g_srcs[Ee];

__device__ __forceinline__ float bn_scale(float g) { return g * rsqrtf(1.0f + 1e-5f); }

// ---- f32x2 packed helpers (sm_103a) ----
__device__ __forceinline__ ull pk(float a, float b) {
    ull r; asm("mov.b64 %0,{%1,%2};" : "=l"(r) : "f"(a), "f"(b)); return r;
}
__device__ __forceinline__ void upk(ull v, float& a, float& b) {
    asm("mov.b64 {%0,%1},%2;" : "=f"(a), "=f"(b) : "l"(v));
}
__device__ __forceinline__ ull f2fma(ull a, ull b, ull c) {
    ull d; asm("fma.rn.f32x2 %0,%1,%2,%3;" : "=l"(d) : "l"(a), "l"(b), "l"(c)); return d;
}

// ---- tf32 helpers ----
__device__ __forceinline__ unsigned tf32u(float f) {
    unsigned r; asm("cvt.rna.tf32.f32 %0,%1;" : "=r"(r) : "f"(f)); return r;
}
__device__ __forceinline__ float tf32f(float f) {
    return __uint_as_float(tf32u(f));
}
__device__ __forceinline__ void mma_tf32(float* d, const unsigned* a, unsigned b0, unsigned b1) {
    asm volatile(
        "mma.sync.aligned.m16n8k8.row.col.f32.tf32.tf32.f32 "
        "{%0,%1,%2,%3},{%4,%5,%6,%7},{%8,%9},{%0,%1,%2,%3};"
        : "+f"(d[0]), "+f"(d[1]), "+f"(d[2]), "+f"(d[3])
        : "r"(a[0]), "r"(a[1]), "r"(a[2]), "r"(a[3]), "r"(b0), "r"(b1));
}

// ---------------- GEMM with fused epilogues ----------------------------------
__global__ void gemm_nt(const float* __restrict__ A,
                        const float* __restrict__ B1, const float* __restrict__ bias1,
                        float* __restrict__ C1, int M1,
                        const float* __restrict__ B2, const float* __restrict__ bias2,
                        float* __restrict__ C2, int M2,
                        int Nr, int K, int mode,
                        const float* __restrict__ epA, const float* __restrict__ epH,
                        const float* __restrict__ epG, const float* __restrict__ epB) {
    __shared__ float As[16][66];
    __shared__ ull   Bs[16][66];
    const int tx = threadIdx.x, ty = threadIdx.y;
    const int tid = ty * 16 + tx;
    const int r0 = blockIdx.y * 64;
    const int c0 = blockIdx.x * 64;
    const int Mtot = M1 + M2;
    ull acc[2][4];
    #pragma unroll
    for (int i = 0; i < 2; i++)
        #pragma unroll
        for (int j = 0; j < 4; j++) acc[i][j] = 0ull;

    for (int kt = 0; kt < K; kt += 16) {
        #pragma unroll
        for (int i = 0; i < 4; i++) {
            int idx = tid + i * 256;
            int kk = idx & 15;
            int rr = idx >> 4;
            As[kk][rr] = A[(r0 + rr) * K + kt + kk];
            int cc = c0 + rr;
            float bv = 0.0f;
            if (cc < Mtot) {
                const float* Brow = (cc < M1) ? (B1 + (size_t)cc * K)
                                              : (B2 + (size_t)(cc - M1) * K);
                bv = Brow[kt + kk];
            }
            Bs[kk][rr] = pk(bv, bv);
        }
        __syncthreads();
        #pragma unroll
        for (int kk = 0; kk < 16; kk++) {
            ull a01 = *(const ull*)&As[kk][ty * 4];
            ull a23 = *(const ull*)&As[kk][ty * 4 + 2];
            #pragma unroll
            for (int j = 0; j < 4; j++) {
                ull b = Bs[kk][tx + 16 * j];
                acc[0][j] = f2fma(a01, b, acc[0][j]);
                acc[1][j] = f2fma(a23, b, acc[1][j]);
            }
        }
        __syncthreads();
    }
    #pragma unroll
    for (int j = 0; j < 4; j++) {
        int c = c0 + tx + 16 * j;
        if (c >= Mtot) continue;
        float bsv;
        float* Cp;
        int ld;
        int cc;
        if (c < M1) { bsv = bias1 ? bias1[c] : 0.0f; Cp = C1; ld = M1; cc = c; }
        else        { bsv = bias2 ? bias2[c - M1] : 0.0f; Cp = C2; ld = M2; cc = c - M1; }
        float v[4];
        upk(acc[0][j], v[0], v[1]);
        upk(acc[1][j], v[2], v[3]);
        int rb = r0 + ty * 4;
        float gs = 0.0f, gb = 0.0f;
        if (mode >= 2) { gs = bn_scale(epG[c]); gb = epB[c]; }
        #pragma unroll
        for (int i = 0; i < 4; i++) {
            int r = rb + i;
            float val = v[i] + bsv;
            if (mode == 1) val = fmaxf(val, 0.0f);
            else if (mode == 2) val = epA[(size_t)r*ld+cc] + (val + epH[(size_t)r*ld+cc]) * gs + gb;
            else if (mode == 3) val = fmaxf((epA[(size_t)r*ld+cc] + val) * gs + gb + epH[(size_t)r*ld+cc], 0.0f);
            Cp[(size_t)r * ld + cc] = val;
        }
    }
}

// ---------------- CSR build ----------------
__global__ void csr_hist(const int* __restrict__ ei) {
    __shared__ int hist[Nn];
    const int t = threadIdx.x;
    for (int i = t; i < Nn; i += 256) hist[i] = 0;
    __syncthreads();
    const int base = blockIdx.x * 4096;
    #pragma unroll 4
    for (int i = t; i < 4096; i += 256)
        atomicAdd(&hist[ei[Ee + base + i]], 1);
    __syncthreads();
    for (int i = t; i < Nn; i += 256) {
        int v = hist[i];
        if (v) atomicAdd(&g_cnt[i], v);
    }
}

__global__ void csr_scan() {
    __shared__ int sm[1024];
    int t = threadIdx.x;
    int b = t * 4;
    int c0 = g_cnt[b], c1 = g_cnt[b+1], c2 = g_cnt[b+2], c3 = g_cnt[b+3];
    int s1 = c0 + c1, s2 = s1 + c2, s3 = s2 + c3;
    sm[t] = s3;
    __syncthreads();
    for (int off = 1; off < 1024; off <<= 1) {
        int v = (t >= off) ? sm[t - off] : 0;
        __syncthreads();
        sm[t] += v;
        __syncthreads();
    }
    int excl = sm[t] - s3;
    g_rowptr[b]   = excl;
    g_rowptr[b+1] = excl + c0;
    g_rowptr[b+2] = excl + s1;
    g_rowptr[b+3] = excl + s2;
    g_cursor[b]   = excl;
    g_cursor[b+1] = excl + c0;
    g_cursor[b+2] = excl + s1;
    g_cursor[b+3] = excl + s2;
    if (t == 1023) g_rowptr[Nn] = sm[1023];
}

__global__ void csr_scatter(const int* __restrict__ ei) {
    int e = blockIdx.x * blockDim.x + threadIdx.x;
    if (e >= Ee) return;
    int d = ei[Ee + e];
    int pos = atomicAdd(&g_cursor[d], 1);
    g_srcs[pos] = ei[e];
}

// ---------------- GAT: per-node attention logits ----------------
__global__ void att_logits(const float* __restrict__ asrc, const float* __restrict__ adst) {
    int i = blockIdx.x * blockDim.x + threadIdx.x;
    if (i >= Nn * NHEADS) return;
    int n = i >> 2, hd = i & 3;
    const float4* xp = (const float4*)&g_xp[n * Hh + hd * DHd];
    const float4* as = (const float4*)&asrc[hd * DHd];
    const float4* ad = (const float4*)&adst[hd * DHd];
    float s = 0.0f, t = 0.0f;
    #pragma unroll
    for (int d4 = 0; d4 < 8; d4++) {
        float4 v = xp[d4], a = as[d4], b = ad[d4];
        s += v.x*a.x + v.y*a.y + v.z*a.z + v.w*a.w;
        t += v.x*b.x + v.y*b.y + v.z*b.z + v.w*b.w;
    }
    g_als[i] = s;
    g_ald[i] = t;
}

__device__ __forceinline__ float leaky(float x) { return x >= 0.0f ? x : 0.2f * x; }

struct FlashSmem {
    float Ks[64][36];
    float Vs[64][40];
    float Ps[4][16][68];
};

// ---------------- FAT kernel: blocks [0,1024) = flash, [1024,5120) = GAT -----
__global__ void __launch_bounds__(128) gat_flash(
        const float* __restrict__ bias, const float* __restrict__ g0,
        const float* __restrict__ b0) {
    __shared__ FlashSmem sm;
    const int t = threadIdx.x;
    const float NEGINF = -__int_as_float(0x7f800000);

    if (blockIdx.x < FLASHBLK) {
        // =========== tensor-core flash attention (tf32 mma) ===========
        const int fb = blockIdx.x;
        const int qt = fb & 63;
        const int hd = (fb >> 6) & 3;
        const int sp = fb >> 8;
        const int w = t >> 5, lane = t & 31;
        const int gi = lane >> 2, li = lane & 3;
        const int q0 = qt * 64 + w * 16;
        const int kbase = sp * (Nn / KSPLIT);

        unsigned qa[4][4];
        {
            const float scq = 0.17677669529663687f;
            #pragma unroll
            for (int ks = 0; ks < 4; ks++) {
                int c = hd * 32 + ks * 8 + li;
                qa[ks][0] = tf32u(g_qkv[(q0+gi  )*384 + c] * scq);
                qa[ks][1] = tf32u(g_qkv[(q0+gi+8)*384 + c] * scq);
                qa[ks][2] = tf32u(g_qkv[(q0+gi  )*384 + c+4] * scq);
                qa[ks][3] = tf32u(g_qkv[(q0+gi+8)*384 + c+4] * scq);
            }
        }

        float4 kst[4], vst[4];
        auto ldg_tile = [&](int ti) {
            int kb = kbase + ti * 64;
            #pragma unroll
            for (int i = 0; i < 4; i++) {
                int c = t + i * 128;
                int j = c >> 3, d4 = c & 7;
                const float4* p = (const float4*)&g_qkv[(kb + j) * 384 + 128 + hd * 32 + d4 * 4];
                kst[i] = p[0];
                vst[i] = p[32];
            }
        };
        auto sts_tile = [&]() {
            #pragma unroll
            for (int i = 0; i < 4; i++) {
                int c = t + i * 128;
                int j = c >> 3, d4 = c & 7;
                float4 k4 = kst[i], v4 = vst[i];
                k4.x = tf32f(k4.x); k4.y = tf32f(k4.y); k4.z = tf32f(k4.z); k4.w = tf32f(k4.w);
                v4.x = tf32f(v4.x); v4.y = tf32f(v4.y); v4.z = tf32f(v4.z); v4.w = tf32f(v4.w);
                *(float4*)&sm.Ks[j][d4 * 4] = k4;
                *(float4*)&sm.Vs[j][d4 * 4] = v4;
            }
        };

        float mxl = NEGINF, mxh = NEGINF, lsl = 0.0f, lsh = 0.0f;
        float o[4][4];
        #pragma unroll
        for (int jn = 0; jn < 4; jn++)
            #pragma unroll
            for (int i = 0; i < 4; i++) o[jn][i] = 0.0f;

        ldg_tile(0);
        for (int ti = 0; ti < NTILES; ti++) {
            __syncthreads();
            sts_tile();
            if (ti + 1 < NTILES) ldg_tile(ti + 1);
            __syncthreads();

            float s[8][4];
            #pragma unroll
            for (int jk = 0; jk < 8; jk++) {
                s[jk][0] = s[jk][1] = s[jk][2] = s[jk][3] = 0.0f;
                #pragma unroll
                for (int ks = 0; ks < 4; ks++) {
                    unsigned b0v = __float_as_uint(sm.Ks[jk*8+gi][ks*8+li]);
                    unsigned b1v = __float_as_uint(sm.Ks[jk*8+gi][ks*8+li+4]);
                    mma_tf32(s[jk], qa[ks], b0v, b1v);
                }
            }
            float tml = NEGINF, tmh = NEGINF;
            #pragma unroll
            for (int jk = 0; jk < 8; jk++) {
                tml = fmaxf(tml, fmaxf(s[jk][0], s[jk][1]));
                tmh = fmaxf(tmh, fmaxf(s[jk][2], s[jk][3]));
            }
            tml = fmaxf(tml, __shfl_xor_sync(0xffffffffu, tml, 1));
            tml = fmaxf(tml, __shfl_xor_sync(0xffffffffu, tml, 2));
            tmh = fmaxf(tmh, __shfl_xor_sync(0xffffffffu, tmh, 1));
            tmh = fmaxf(tmh, __shfl_xor_sync(0xffffffffu, tmh, 2));
            float nml = fmaxf(mxl, tml), nmh = fmaxf(mxh, tmh);
            float scl = __expf(mxl - nml), sch = __expf(mxh - nmh);
            mxl = nml; mxh = nmh;
            lsl *= scl; lsh *= sch;
            #pragma unroll
            for (int jn = 0; jn < 4; jn++) {
                o[jn][0] *= scl; o[jn][1] *= scl;
                o[jn][2] *= sch; o[jn][3] *= sch;
            }
            float rsl = 0.0f, rsh = 0.0f;
            #pragma unroll
            for (int jk = 0; jk < 8; jk++) {
                float p0 = __expf(s[jk][0] - mxl), p1 = __expf(s[jk][1] - mxl);
                float p2 = __expf(s[jk][2] - mxh), p3 = __expf(s[jk][3] - mxh);
                rsl += p0 + p1; rsh += p2 + p3;
                float2 lo = make_float2(tf32f(p0), tf32f(p1));
                float2 hi = make_float2(tf32f(p2), tf32f(p3));
                *(float2*)&sm.Ps[w][gi  ][jk*8 + 2*li] = lo;
                *(float2*)&sm.Ps[w][gi+8][jk*8 + 2*li] = hi;
            }
            rsl += __shfl_xor_sync(0xffffffffu, rsl, 1);
            rsl += __shfl_xor_sync(0xffffffffu, rsl, 2);
            rsh += __shfl_xor_sync(0xffffffffu, rsh, 1);
            rsh += __shfl_xor_sync(0xffffffffu, rsh, 2);
            lsl += rsl; lsh += rsh;
            __syncwarp();
            #pragma unroll
            for (int kk = 0; kk < 8; kk++) {
                unsigned pa[4];
                pa[0] = __float_as_uint(sm.Ps[w][gi  ][kk*8 + li]);
                pa[1] = __float_as_uint(sm.Ps[w][gi+8][kk*8 + li]);
                pa[2] = __float_as_uint(sm.Ps[w][gi  ][kk*8 + li + 4]);
                pa[3] = __float_as_uint(sm.Ps[w][gi+8][kk*8 + li + 4]);
                #pragma unroll
                for (int jn = 0; jn < 4; jn++) {
                    unsigned b0v = __float_as_uint(sm.Vs[kk*8+li  ][jn*8+gi]);
                    unsigned b1v = __float_as_uint(sm.Vs[kk*8+li+4][jn*8+gi]);
                    mma_tf32(o[jn], pa, b0v, b1v);
                }
            }
            __syncwarp();
        }

        const int nl = q0 + gi, nh = nl + 8;
        const int qhl = nl * 4 + hd, qhh = nh * 4 + hd;
        if (li == 0) {
            g_pm[sp * NQH + qhl] = mxl;
            g_pl[sp * NQH + qhl] = lsl;
            g_pm[sp * NQH + qhh] = mxh;
            g_pl[sp * NQH + qhh] = lsh;
        }
        #pragma unroll
        for (int jn = 0; jn < 4; jn++) {
            int dh = jn * 8 + 2 * li;
            *(float2*)&g_pacc[((size_t)sp * NQH + qhl) * DHd + dh] = make_float2(o[jn][0], o[jn][1]);
            *(float2*)&g_pacc[((size_t)sp * NQH + qhh) * DHd + dh] = make_float2(o[jn][2], o[jn][3]);
        }
    } else {
        // =========== GAT aggregation: warp w = head w, lane = channel ===========
        const int d = blockIdx.x - FLASHBLK;
        const int w = t >> 5, lane = t & 31;
        const int beg = g_rowptr[d], end = g_rowptr[d + 1];
        const float adh = g_ald[d * 4 + w];

        // pass 1: warp-level max of leaky logits for head w
        float mx = NEGINF;
        for (int e = beg + lane; e < end; e += 32) {
            int s = g_srcs[e];
            mx = fmaxf(mx, leaky(g_als[s * 4 + w] + adh));
        }
        #pragma unroll
        for (int off = 16; off > 0; off >>= 1)
            mx = fmaxf(mx, __shfl_xor_sync(0xffffffffu, mx, off));

        // pass 2: chunks of 32 edges, weights broadcast via shfl
        float den = 0.0f;
        float acc = 0.0f;
        const int c = w * 32 + lane;   // output channel
        for (int cb = beg; cb < end; cb += 32) {
            int cnt = min(32, end - cb);
            int e = cb + lane;
            float wgt = 0.0f;
            int ssrc = 0;
            if (lane < cnt) {
                ssrc = g_srcs[e];
                wgt = __expf(leaky(g_als[ssrc * 4 + w] + adh) - mx);
            }
            den += wgt;
            for (int j = 0; j < cnt; j++) {
                float wj = __shfl_sync(0xffffffffu, wgt, j);
                int sj   = __shfl_sync(0xffffffffu, ssrc, j);
                acc = fmaf(wj, g_xp[sj * Hh + c], acc);
            }
        }
        #pragma unroll
        for (int off = 16; off > 0; off >>= 1)
            den += __shfl_xor_sync(0xffffffffu, den, off);

        float v = acc / (den + 1e-16f) + bias[c] + g_h[d * Hh + c];
        g_hloc[d * Hh + c] = v * bn_scale(g0[c]) + b0[c];
    }
}

// merge split-K partials: thread per (qh, d)
__global__ void flash_merge() {
    int i = blockIdx.x * blockDim.x + threadIdx.x;
    if (i >= NQH * DHd) return;
    int qh = i >> 5;
    int d = i & 31;
    float ms[KSPLIT];
    float M = -__int_as_float(0x7f800000);
    #pragma unroll
    for (int s = 0; s < KSPLIT; s++) { ms[s] = g_pm[s*NQH+qh]; M = fmaxf(M, ms[s]); }
    float L = 0.0f, a = 0.0f;
    #pragma unroll
    for (int s = 0; s < KSPLIT; s++) {
        float w = __expf(ms[s] - M);
        L += g_pl[s*NQH+qh] * w;
        a += g_pacc[((size_t)s*NQH+qh)*DHd + d] * w;
    }
    int n = qh >> 2, hd = qh & 3;
    g_attn[n * Hh + hd * DHd + d] = a / L;
}

// ---------------- host launch ----------------
extern "C" void kernel_launch(void* const* d_in, const int* in_sizes, int n_in,
                              void* d_out, int out_size) {
    const float* x       = (const float*)d_in[0];
    const int*   ei      = (const int*)d_in[1];
    const float* w_in    = (const float*)d_in[2];
    const float* b_in    = (const float*)d_in[3];
    const float* w_gat   = (const float*)d_in[4];
    const float* att_src = (const float*)d_in[5];
    const float* att_dst = (const float*)d_in[6];
    const float* b_gat   = (const float*)d_in[7];
    const float* w_qkv   = (const float*)d_in[8];
    const float* b_qkv   = (const float*)d_in[9];
    const float* w_o     = (const float*)d_in[10];
    const float* b_o     = (const float*)d_in[11];
    const float* bn_g    = (const float*)d_in[12];
    const float* bn_b    = (const float*)d_in[13];
    const float* w1      = (const float*)d_in[14];
    const float* b1      = (const float*)d_in[15];
    const float* w2      = (const float*)d_in[16];
    const float* b2      = (const float*)d_in[17];
    const float* w_out   = (const float*)d_in[18];
    const float* b_out   = (const float*)d_in[19];
    float* out = (float*)d_out;

    float *p_h, *p_xp, *p_qkv, *p_attn, *p_out, *p_t1, *p_hloc;
    int* p_cnt;
    cudaGetSymbolAddress((void**)&p_h,    g_h);
    cudaGetSymbolAddress((void**)&p_xp,   g_xp);
    cudaGetSymbolAddress((void**)&p_qkv,  g_qkv);
    cudaGetSymbolAddress((void**)&p_attn, g_attn);
    cudaGetSymbolAddress((void**)&p_out,  g_out);
    cudaGetSymbolAddress((void**)&p_t1,   g_t1);
    cudaGetSymbolAddress((void**)&p_hloc, g_hloc);
    cudaGetSymbolAddress((void**)&p_cnt,  g_cnt);

    dim3 gblk(16, 16);

    // CSR build
    cudaMemsetAsync(p_cnt, 0, Nn * sizeof(int));
    csr_hist<<<Ee / 4096, 256>>>(ei);
    csr_scan<<<1, 1024>>>();
    csr_scatter<<<(Ee + 255) / 256, 256>>>(ei);

    // input projection: h = relu(x @ w_in^T + b_in)
    gemm_nt<<<dim3(2, 64), gblk>>>(x, w_in, b_in, p_h, Hh,
                                   nullptr, nullptr, nullptr, 0, Nn, IND, 1,
                                   nullptr, nullptr, nullptr, nullptr);

    for (int l = 0; l < Ll; l++) {
        // fused GAT projection + QKV projection
        gemm_nt<<<dim3(8, 64), gblk>>>(p_h,
                                       w_gat + l * Hh * Hh, nullptr, p_xp, Hh,
                                       w_qkv + l * 3 * Hh * Hh, b_qkv + l * 3 * Hh, p_qkv, 3 * Hh,
                                       Nn, Hh, 0, nullptr, nullptr, nullptr, nullptr);
        att_logits<<<(Nn * NHEADS + 127) / 128, 128>>>(att_src + l * Hh, att_dst + l * Hh);

        // FAT kernel: flash attention (1024 blocks, first) + GAT aggregation (4096 blocks)
        gat_flash<<<FLASHBLK + Nn, 128>>>(b_gat + l * Hh,
                                          bn_g + (l * 3 + 0) * Hh, bn_b + (l * 3 + 0) * Hh);
        flash_merge<<<(NQH * DHd + 255) / 256, 256>>>();

        // w_o GEMM with fused combine_att epilogue -> g_out
        gemm_nt<<<dim3(2, 64), gblk>>>(p_attn, w_o + l * Hh * Hh, b_o + l * Hh, p_out, Hh,
                                       nullptr, nullptr, nullptr, 0, Nn, Hh, 2,
                                       p_hloc, p_h,
                                       bn_g + (l * 3 + 1) * Hh, bn_b + (l * 3 + 1) * Hh);

        // MLP
        gemm_nt<<<dim3(4, 64), gblk>>>(p_out, w1 + l * 2 * Hh * Hh, b1 + l * 2 * Hh, p_t1, 2 * Hh,
                                       nullptr, nullptr, nullptr, 0, Nn, Hh, 1,
                                       nullptr, nullptr, nullptr, nullptr);
        // w2 GEMM with fused final_combine epilogue -> g_h
        gemm_nt<<<dim3(2, 64), gblk>>>(p_t1, w2 + l * 2 * Hh * Hh, b2 + l * Hh, p_h, Hh,
                                       nullptr, nullptr, nullptr, 0, Nn, 2 * Hh, 3,
                                       p_out, p_h,
                                       bn_g + (l * 3 + 2) * Hh, bn_b + (l * 3 + 2) * Hh);
    }

    // output projection -> [4096, 2]
    gemm_nt<<<dim3(1, 64), gblk>>>(p_h, w_out, b_out, out, 2,
                                   nullptr, nullptr, nullptr, 0, Nn, Hh, 0,
                                   nullptr, nullptr, nullptr, nullptr);
}

// round 7
// speedup vs baseline: 6.4676x; 1.2023x over previous
#include <cuda_runtime.h>
#include <math.h>

#define Nn 4096
#define Ee 262144
#define IND 64
#define Hh 128
#define NHEADS 4
#define DHd 32
#define Ll 2
#define KSPLIT 4
#define NQH (Nn * NHEADS)
#define FLASHBLK ((Nn / 64) * NHEADS * KSPLIT)   // 1024
#define NTILES ((Nn / KSPLIT) / 64)              // 16

typedef unsigned long long ull;

// ---------------- scratch (static device globals; no allocation) -------------
__device__ float g_h[Nn*Hh];
__device__ float g_xp[Nn*Hh];
__device__ float g_als[Nn*NHEADS];
__device__ float g_ald[Nn*NHEADS];
__device__ float g_hloc[Nn*Hh];
__device__ float g_qkv[Nn*3*Hh];
__device__ float g_attn[Nn*Hh];
__device__ float g_out[Nn*Hh];
__device__ float g_t1[Nn*2*Hh];
// flash split-K partials
__device__ float g_pm[KSPLIT*NQH];
__device__ float g_pl[KSPLIT*NQH];
__device__ float g_pacc[KSPLIT*NQH*DHd];
// CSR
__device__ int g_cnt[Nn];
__device__ int g_cursor[Nn];
__device__ int g_rowptr[Nn+1];
__device__ int g_srcs[Ee];

__device__ __forceinline__ float bn_scale(float g) { return g * rsqrtf(1.0f + 1e-5f); }

// ---- f32x2 packed helpers (sm_103a) ----
__device__ __forceinline__ ull pk(float a, float b) {
    ull r; asm("mov.b64 %0,{%1,%2};" : "=l"(r) : "f"(a), "f"(b)); return r;
}
__device__ __forceinline__ void upk(ull v, float& a, float& b) {
    asm("mov.b64 {%0,%1},%2;" : "=f"(a), "=f"(b) : "l"(v));
}
__device__ __forceinline__ ull f2fma(ull a, ull b, ull c) {
    ull d; asm("fma.rn.f32x2 %0,%1,%2,%3;" : "=l"(d) : "l"(a), "l"(b), "l"(c)); return d;
}

// ---- tf32 helpers ----
__device__ __forceinline__ unsigned tf32u(float f) {
    unsigned r; asm("cvt.rna.tf32.f32 %0,%1;" : "=r"(r) : "f"(f)); return r;
}
__device__ __forceinline__ float tf32f(float f) {
    return __uint_as_float(tf32u(f));
}
__device__ __forceinline__ void mma_tf32(float* d, const unsigned* a, unsigned b0, unsigned b1) {
    asm volatile(
        "mma.sync.aligned.m16n8k8.row.col.f32.tf32.tf32.f32 "
        "{%0,%1,%2,%3},{%4,%5,%6,%7},{%8,%9},{%0,%1,%2,%3};"
        : "+f"(d[0]), "+f"(d[1]), "+f"(d[2]), "+f"(d[3])
        : "r"(a[0]), "r"(a[1]), "r"(a[2]), "r"(a[3]), "r"(b0), "r"(b1));
}

// ---------------- tf32 tensor-core GEMM, Nr fixed = 4096 ---------------------
// C1[*,M1] = A @ B1^T (+bias1) cols [0,M1);  C2[*,M2] = A @ B2^T (+bias2) cols [M1,M1+M2)
// mode 0: none   1: relu
// mode 2: C1 = epA + (acc+bias + epH) * bn_scale(epG) + epB
// mode 3: C1 = max((epA + acc+bias) * bn_scale(epG) + epB + epH, 0)
__global__ void __launch_bounds__(256) gemm_tf32(
        const float* __restrict__ A,
        const float* __restrict__ B1, const float* __restrict__ bias1,
        float* __restrict__ C1, int M1,
        const float* __restrict__ B2, const float* __restrict__ bias2,
        float* __restrict__ C2, int M2,
        int K, int mode,
        const float* __restrict__ epA, const float* __restrict__ epH,
        const float* __restrict__ epG, const float* __restrict__ epB) {
    __shared__ float As[128][36];
    __shared__ float Bs[64][36];
    const int t = threadIdx.x;
    const int w = t >> 5, lane = t & 31;
    const int gi = lane >> 2, li = lane & 3;
    const int wr = w >> 1, wc = w & 1;
    const int r0 = blockIdx.y * 128;
    const int c0 = blockIdx.x * 64;
    const int Mtot = M1 + M2;

    float o[2][4][4];
    #pragma unroll
    for (int mt = 0; mt < 2; mt++)
        #pragma unroll
        for (int nt = 0; nt < 4; nt++)
            #pragma unroll
            for (int i = 0; i < 4; i++) o[mt][nt][i] = 0.0f;

    for (int kc = 0; kc < K; kc += 32) {
        // stage A chunk 128x32 (tf32-rounded)
        #pragma unroll
        for (int i = 0; i < 4; i++) {
            int id = t + i * 256;
            int row = id >> 3, kq = id & 7;
            float4 v = *(const float4*)&A[(size_t)(r0 + row) * K + kc + kq * 4];
            v.x = tf32f(v.x); v.y = tf32f(v.y); v.z = tf32f(v.z); v.w = tf32f(v.w);
            *(float4*)&As[row][kq * 4] = v;
        }
        // stage B chunk 64x32
        #pragma unroll
        for (int i = 0; i < 2; i++) {
            int id = t + i * 256;
            int row = id >> 3, kq = id & 7;
            int cc = c0 + row;
            float4 v = make_float4(0.f, 0.f, 0.f, 0.f);
            if (cc < Mtot) {
                const float* Brow = (cc < M1) ? (B1 + (size_t)cc * K)
                                              : (B2 + (size_t)(cc - M1) * K);
                v = *(const float4*)&Brow[kc + kq * 4];
            }
            v.x = tf32f(v.x); v.y = tf32f(v.y); v.z = tf32f(v.z); v.w = tf32f(v.w);
            *(float4*)&Bs[row][kq * 4] = v;
        }
        __syncthreads();
        #pragma unroll
        for (int k8 = 0; k8 < 32; k8 += 8) {
            unsigned a[2][4];
            #pragma unroll
            for (int mt = 0; mt < 2; mt++) {
                int row = wr * 32 + mt * 16;
                a[mt][0] = __float_as_uint(As[row + gi    ][k8 + li]);
                a[mt][1] = __float_as_uint(As[row + gi + 8][k8 + li]);
                a[mt][2] = __float_as_uint(As[row + gi    ][k8 + li + 4]);
                a[mt][3] = __float_as_uint(As[row + gi + 8][k8 + li + 4]);
            }
            unsigned b[4][2];
            #pragma unroll
            for (int nt = 0; nt < 4; nt++) {
                int col = wc * 32 + nt * 8;
                b[nt][0] = __float_as_uint(Bs[col + gi][k8 + li]);
                b[nt][1] = __float_as_uint(Bs[col + gi][k8 + li + 4]);
            }
            #pragma unroll
            for (int mt = 0; mt < 2; mt++)
                #pragma unroll
                for (int nt = 0; nt < 4; nt++)
                    mma_tf32(o[mt][nt], a[mt], b[nt][0], b[nt][1]);
        }
        __syncthreads();
    }

    // epilogue
    #pragma unroll
    for (int nt = 0; nt < 4; nt++) {
        int c = c0 + wc * 32 + nt * 8 + 2 * li;
        if (c >= Mtot) continue;
        const float* bias; float* Cp; int ld, cc;
        if (c < M1) { bias = bias1; Cp = C1; ld = M1; cc = c; }
        else        { bias = bias2; Cp = C2; ld = M2; cc = c - M1; }
        float b0v = bias ? bias[cc] : 0.0f;
        float b1v = bias ? bias[cc + 1] : 0.0f;
        float gs0 = 0.f, gs1 = 0.f, gb0 = 0.f, gb1 = 0.f;
        if (mode >= 2) {
            gs0 = bn_scale(epG[c]); gs1 = bn_scale(epG[c + 1]);
            gb0 = epB[c]; gb1 = epB[c + 1];
        }
        #pragma unroll
        for (int mt = 0; mt < 2; mt++) {
            #pragma unroll
            for (int half = 0; half < 2; half++) {
                int r = r0 + wr * 32 + mt * 16 + gi + half * 8;
                float v0 = o[mt][nt][half * 2]     + b0v;
                float v1 = o[mt][nt][half * 2 + 1] + b1v;
                if (mode == 1) { v0 = fmaxf(v0, 0.f); v1 = fmaxf(v1, 0.f); }
                else if (mode == 2) {
                    float2 ea = *(const float2*)&epA[(size_t)r * ld + cc];
                    float2 eh = *(const float2*)&epH[(size_t)r * ld + cc];
                    v0 = ea.x + (v0 + eh.x) * gs0 + gb0;
                    v1 = ea.y + (v1 + eh.y) * gs1 + gb1;
                } else if (mode == 3) {
                    float2 ea = *(const float2*)&epA[(size_t)r * ld + cc];
                    float2 eh = *(const float2*)&epH[(size_t)r * ld + cc];
                    v0 = fmaxf((ea.x + v0) * gs0 + gb0 + eh.x, 0.f);
                    v1 = fmaxf((ea.y + v1) * gs1 + gb1 + eh.y, 0.f);
                }
                *(float2*)&Cp[(size_t)r * ld + cc] = make_float2(v0, v1);
            }
        }
    }
}

// ---------------- scalar GEMM (final tiny projection only) -------------------
__global__ void gemm_nt(const float* __restrict__ A,
                        const float* __restrict__ B1, const float* __restrict__ bias1,
                        float* __restrict__ C1, int M1, int Nr, int K) {
    __shared__ float As[16][66];
    __shared__ ull   Bs[16][66];
    const int tx = threadIdx.x, ty = threadIdx.y;
    const int tid = ty * 16 + tx;
    const int r0 = blockIdx.y * 64;
    ull acc[2][4];
    #pragma unroll
    for (int i = 0; i < 2; i++)
        #pragma unroll
        for (int j = 0; j < 4; j++) acc[i][j] = 0ull;

    for (int kt = 0; kt < K; kt += 16) {
        #pragma unroll
        for (int i = 0; i < 4; i++) {
            int idx = tid + i * 256;
            int kk = idx & 15;
            int rr = idx >> 4;
            As[kk][rr] = A[(r0 + rr) * K + kt + kk];
            float bv = (rr < M1) ? B1[(size_t)rr * K + kt + kk] : 0.0f;
            Bs[kk][rr] = pk(bv, bv);
        }
        __syncthreads();
        #pragma unroll
        for (int kk = 0; kk < 16; kk++) {
            ull a01 = *(const ull*)&As[kk][ty * 4];
            ull a23 = *(const ull*)&As[kk][ty * 4 + 2];
            #pragma unroll
            for (int j = 0; j < 4; j++) {
                ull b = Bs[kk][tx + 16 * j];
                acc[0][j] = f2fma(a01, b, acc[0][j]);
                acc[1][j] = f2fma(a23, b, acc[1][j]);
            }
        }
        __syncthreads();
    }
    #pragma unroll
    for (int j = 0; j < 4; j++) {
        int c = tx + 16 * j;
        if (c >= M1) continue;
        float bsv = bias1 ? bias1[c] : 0.0f;
        float v0, v1, v2, v3;
        upk(acc[0][j], v0, v1);
        upk(acc[1][j], v2, v3);
        int r = r0 + ty * 4;
        C1[(size_t)(r + 0) * M1 + c] = v0 + bsv;
        C1[(size_t)(r + 1) * M1 + c] = v1 + bsv;
        C1[(size_t)(r + 2) * M1 + c] = v2 + bsv;
        C1[(size_t)(r + 3) * M1 + c] = v3 + bsv;
    }
}

// ---------------- CSR build ----------------
__global__ void csr_hist(const int* __restrict__ ei) {
    __shared__ int hist[Nn];
    const int t = threadIdx.x;
    for (int i = t; i < Nn; i += 256) hist[i] = 0;
    __syncthreads();
    const int base = blockIdx.x * 4096;
    #pragma unroll 4
    for (int i = t; i < 4096; i += 256)
        atomicAdd(&hist[ei[Ee + base + i]], 1);
    __syncthreads();
    for (int i = t; i < Nn; i += 256) {
        int v = hist[i];
        if (v) atomicAdd(&g_cnt[i], v);
    }
}

__global__ void csr_scan() {
    __shared__ int sm[1024];
    int t = threadIdx.x;
    int b = t * 4;
    int c0 = g_cnt[b], c1 = g_cnt[b+1], c2 = g_cnt[b+2], c3 = g_cnt[b+3];
    int s1 = c0 + c1, s2 = s1 + c2, s3 = s2 + c3;
    sm[t] = s3;
    __syncthreads();
    for (int off = 1; off < 1024; off <<= 1) {
        int v = (t >= off) ? sm[t - off] : 0;
        __syncthreads();
        sm[t] += v;
        __syncthreads();
    }
    int excl = sm[t] - s3;
    g_rowptr[b]   = excl;
    g_rowptr[b+1] = excl + c0;
    g_rowptr[b+2] = excl + s1;
    g_rowptr[b+3] = excl + s2;
    g_cursor[b]   = excl;
    g_cursor[b+1] = excl + c0;
    g_cursor[b+2] = excl + s1;
    g_cursor[b+3] = excl + s2;
    if (t == 1023) g_rowptr[Nn] = sm[1023];
}

__global__ void csr_scatter(const int* __restrict__ ei) {
    int e = blockIdx.x * blockDim.x + threadIdx.x;
    if (e >= Ee) return;
    int d = ei[Ee + e];
    int pos = atomicAdd(&g_cursor[d], 1);
    g_srcs[pos] = ei[e];
}

// ---------------- GAT: per-node attention logits ----------------
__global__ void att_logits(const float* __restrict__ asrc, const float* __restrict__ adst) {
    int i = blockIdx.x * blockDim.x + threadIdx.x;
    if (i >= Nn * NHEADS) return;
    int n = i >> 2, hd = i & 3;
    const float4* xp = (const float4*)&g_xp[n * Hh + hd * DHd];
    const float4* as = (const float4*)&asrc[hd * DHd];
    const float4* ad = (const float4*)&adst[hd * DHd];
    float s = 0.0f, t = 0.0f;
    #pragma unroll
    for (int d4 = 0; d4 < 8; d4++) {
        float4 v = xp[d4], a = as[d4], b = ad[d4];
        s += v.x*a.x + v.y*a.y + v.z*a.z + v.w*a.w;
        t += v.x*b.x + v.y*b.y + v.z*b.z + v.w*b.w;
    }
    g_als[i] = s;
    g_ald[i] = t;
}

__device__ __forceinline__ float leaky(float x) { return x >= 0.0f ? x : 0.2f * x; }

struct FlashSmem {
    float Ks[64][36];
    float Vs[64][40];
    float Ps[4][16][68];
};

// ---------------- FAT kernel: blocks [0,1024) = flash, [1024,5120) = GAT -----
__global__ void __launch_bounds__(128) gat_flash(
        const float* __restrict__ bias, const float* __restrict__ g0,
        const float* __restrict__ b0) {
    __shared__ FlashSmem sm;
    const int t = threadIdx.x;
    const float NEGINF = -__int_as_float(0x7f800000);

    if (blockIdx.x < FLASHBLK) {
        const int fb = blockIdx.x;
        const int qt = fb & 63;
        const int hd = (fb >> 6) & 3;
        const int sp = fb >> 8;
        const int w = t >> 5, lane = t & 31;
        const int gi = lane >> 2, li = lane & 3;
        const int q0 = qt * 64 + w * 16;
        const int kbase = sp * (Nn / KSPLIT);

        unsigned qa[4][4];
        {
            const float scq = 0.17677669529663687f;
            #pragma unroll
            for (int ks = 0; ks < 4; ks++) {
                int c = hd * 32 + ks * 8 + li;
                qa[ks][0] = tf32u(g_qkv[(q0+gi  )*384 + c] * scq);
                qa[ks][1] = tf32u(g_qkv[(q0+gi+8)*384 + c] * scq);
                qa[ks][2] = tf32u(g_qkv[(q0+gi  )*384 + c+4] * scq);
                qa[ks][3] = tf32u(g_qkv[(q0+gi+8)*384 + c+4] * scq);
            }
        }

        float4 kst[4], vst[4];
        auto ldg_tile = [&](int ti) {
            int kb = kbase + ti * 64;
            #pragma unroll
            for (int i = 0; i < 4; i++) {
                int c = t + i * 128;
                int j = c >> 3, d4 = c & 7;
                const float4* p = (const float4*)&g_qkv[(kb + j) * 384 + 128 + hd * 32 + d4 * 4];
                kst[i] = p[0];
                vst[i] = p[32];
            }
        };
        auto sts_tile = [&]() {
            #pragma unroll
            for (int i = 0; i < 4; i++) {
                int c = t + i * 128;
                int j = c >> 3, d4 = c & 7;
                float4 k4 = kst[i], v4 = vst[i];
                k4.x = tf32f(k4.x); k4.y = tf32f(k4.y); k4.z = tf32f(k4.z); k4.w = tf32f(k4.w);
                v4.x = tf32f(v4.x); v4.y = tf32f(v4.y); v4.z = tf32f(v4.z); v4.w = tf32f(v4.w);
                *(float4*)&sm.Ks[j][d4 * 4] = k4;
                *(float4*)&sm.Vs[j][d4 * 4] = v4;
            }
        };

        float mxl = NEGINF, mxh = NEGINF, lsl = 0.0f, lsh = 0.0f;
        float o[4][4];
        #pragma unroll
        for (int jn = 0; jn < 4; jn++)
            #pragma unroll
            for (int i = 0; i < 4; i++) o[jn][i] = 0.0f;

        ldg_tile(0);
        for (int ti = 0; ti < NTILES; ti++) {
            __syncthreads();
            sts_tile();
            if (ti + 1 < NTILES) ldg_tile(ti + 1);
            __syncthreads();

            float s[8][4];
            #pragma unroll
            for (int jk = 0; jk < 8; jk++) {
                s[jk][0] = s[jk][1] = s[jk][2] = s[jk][3] = 0.0f;
                #pragma unroll
                for (int ks = 0; ks < 4; ks++) {
                    unsigned b0v = __float_as_uint(sm.Ks[jk*8+gi][ks*8+li]);
                    unsigned b1v = __float_as_uint(sm.Ks[jk*8+gi][ks*8+li+4]);
                    mma_tf32(s[jk], qa[ks], b0v, b1v);
                }
            }
            float tml = NEGINF, tmh = NEGINF;
            #pragma unroll
            for (int jk = 0; jk < 8; jk++) {
                tml = fmaxf(tml, fmaxf(s[jk][0], s[jk][1]));
                tmh = fmaxf(tmh, fmaxf(s[jk][2], s[jk][3]));
            }
            tml = fmaxf(tml, __shfl_xor_sync(0xffffffffu, tml, 1));
            tml = fmaxf(tml, __shfl_xor_sync(0xffffffffu, tml, 2));
            tmh = fmaxf(tmh, __shfl_xor_sync(0xffffffffu, tmh, 1));
            tmh = fmaxf(tmh, __shfl_xor_sync(0xffffffffu, tmh, 2));
            float nml = fmaxf(mxl, tml), nmh = fmaxf(mxh, tmh);
            float scl = __expf(mxl - nml), sch = __expf(mxh - nmh);
            mxl = nml; mxh = nmh;
            lsl *= scl; lsh *= sch;
            #pragma unroll
            for (int jn = 0; jn < 4; jn++) {
                o[jn][0] *= scl; o[jn][1] *= scl;
                o[jn][2] *= sch; o[jn][3] *= sch;
            }
            float rsl = 0.0f, rsh = 0.0f;
            #pragma unroll
            for (int jk = 0; jk < 8; jk++) {
                float p0 = __expf(s[jk][0] - mxl), p1 = __expf(s[jk][1] - mxl);
                float p2 = __expf(s[jk][2] - mxh), p3 = __expf(s[jk][3] - mxh);
                rsl += p0 + p1; rsh += p2 + p3;
                float2 lo = make_float2(tf32f(p0), tf32f(p1));
                float2 hi = make_float2(tf32f(p2), tf32f(p3));
                *(float2*)&sm.Ps[w][gi  ][jk*8 + 2*li] = lo;
                *(float2*)&sm.Ps[w][gi+8][jk*8 + 2*li] = hi;
            }
            rsl += __shfl_xor_sync(0xffffffffu, rsl, 1);
            rsl += __shfl_xor_sync(0xffffffffu, rsl, 2);
            rsh += __shfl_xor_sync(0xffffffffu, rsh, 1);
            rsh += __shfl_xor_sync(0xffffffffu, rsh, 2);
            lsl += rsl; lsh += rsh;
            __syncwarp();
            #pragma unroll
            for (int kk = 0; kk < 8; kk++) {
                unsigned pa[4];
                pa[0] = __float_as_uint(sm.Ps[w][gi  ][kk*8 + li]);
                pa[1] = __float_as_uint(sm.Ps[w][gi+8][kk*8 + li]);
                pa[2] = __float_as_uint(sm.Ps[w][gi  ][kk*8 + li + 4]);
                pa[3] = __float_as_uint(sm.Ps[w][gi+8][kk*8 + li + 4]);
                #pragma unroll
                for (int jn = 0; jn < 4; jn++) {
                    unsigned b0v = __float_as_uint(sm.Vs[kk*8+li  ][jn*8+gi]);
                    unsigned b1v = __float_as_uint(sm.Vs[kk*8+li+4][jn*8+gi]);
                    mma_tf32(o[jn], pa, b0v, b1v);
                }
            }
            __syncwarp();
        }

        const int nl = q0 + gi, nh = nl + 8;
        const int qhl = nl * 4 + hd, qhh = nh * 4 + hd;
        if (li == 0) {
            g_pm[sp * NQH + qhl] = mxl;
            g_pl[sp * NQH + qhl] = lsl;
            g_pm[sp * NQH + qhh] = mxh;
            g_pl[sp * NQH + qhh] = lsh;
        }
        #pragma unroll
        for (int jn = 0; jn < 4; jn++) {
            int dh = jn * 8 + 2 * li;
            *(float2*)&g_pacc[((size_t)sp * NQH + qhl) * DHd + dh] = make_float2(o[jn][0], o[jn][1]);
            *(float2*)&g_pacc[((size_t)sp * NQH + qhh) * DHd + dh] = make_float2(o[jn][2], o[jn][3]);
        }
    } else {
        // =========== GAT aggregation: warp w = head w, lane = channel ===========
        const int d = blockIdx.x - FLASHBLK;
        const int w = t >> 5, lane = t & 31;
        const int beg = g_rowptr[d], end = g_rowptr[d + 1];
        const float adh = g_ald[d * 4 + w];

        float mx = NEGINF;
        for (int e = beg + lane; e < end; e += 32) {
            int s = g_srcs[e];
            mx = fmaxf(mx, leaky(g_als[s * 4 + w] + adh));
        }
        #pragma unroll
        for (int off = 16; off > 0; off >>= 1)
            mx = fmaxf(mx, __shfl_xor_sync(0xffffffffu, mx, off));

        float den = 0.0f;
        float acc = 0.0f;
        const int c = w * 32 + lane;
        for (int cb = beg; cb < end; cb += 32) {
            int cnt = min(32, end - cb);
            int e = cb + lane;
            float wgt = 0.0f;
            int ssrc = 0;
            if (lane < cnt) {
                ssrc = g_srcs[e];
                wgt = __expf(leaky(g_als[ssrc * 4 + w] + adh) - mx);
            }
            den += wgt;
            for (int j = 0; j < cnt; j++) {
                float wj = __shfl_sync(0xffffffffu, wgt, j);
                int sj   = __shfl_sync(0xffffffffu, ssrc, j);
                acc = fmaf(wj, g_xp[sj * Hh + c], acc);
            }
        }
        #pragma unroll
        for (int off = 16; off > 0; off >>= 1)
            den += __shfl_xor_sync(0xffffffffu, den, off);

        float v = acc / (den + 1e-16f) + bias[c] + g_h[d * Hh + c];
        g_hloc[d * Hh + c] = v * bn_scale(g0[c]) + b0[c];
    }
}

// merge split-K partials: thread per (qh, d)
__global__ void flash_merge() {
    int i = blockIdx.x * blockDim.x + threadIdx.x;
    if (i >= NQH * DHd) return;
    int qh = i >> 5;
    int d = i & 31;
    float ms[KSPLIT];
    float M = -__int_as_float(0x7f800000);
    #pragma unroll
    for (int s = 0; s < KSPLIT; s++) { ms[s] = g_pm[s*NQH+qh]; M = fmaxf(M, ms[s]); }
    float L = 0.0f, a = 0.0f;
    #pragma unroll
    for (int s = 0; s < KSPLIT; s++) {
        float w = __expf(ms[s] - M);
        L += g_pl[s*NQH+qh] * w;
        a += g_pacc[((size_t)s*NQH+qh)*DHd + d] * w;
    }
    int n = qh >> 2, hd = qh & 3;
    g_attn[n * Hh + hd * DHd + d] = a / L;
}

// ---------------- host launch ----------------
extern "C" void kernel_launch(void* const* d_in, const int* in_sizes, int n_in,
                              void* d_out, int out_size) {
    const float* x       = (const float*)d_in[0];
    const int*   ei      = (const int*)d_in[1];
    const float* w_in    = (const float*)d_in[2];
    const float* b_in    = (const float*)d_in[3];
    const float* w_gat   = (const float*)d_in[4];
    const float* att_src = (const float*)d_in[5];
    const float* att_dst = (const float*)d_in[6];
    const float* b_gat   = (const float*)d_in[7];
    const float* w_qkv   = (const float*)d_in[8];
    const float* b_qkv   = (const float*)d_in[9];
    const float* w_o     = (const float*)d_in[10];
    const float* b_o     = (const float*)d_in[11];
    const float* bn_g    = (const float*)d_in[12];
    const float* bn_b    = (const float*)d_in[13];
    const float* w1      = (const float*)d_in[14];
    const float* b1      = (const float*)d_in[15];
    const float* w2      = (const float*)d_in[16];
    const float* b2      = (const float*)d_in[17];
    const float* w_out   = (const float*)d_in[18];
    const float* b_out   = (const float*)d_in[19];
    float* out = (float*)d_out;

    float *p_h, *p_xp, *p_qkv, *p_attn, *p_out, *p_t1, *p_hloc;
    int* p_cnt;
    cudaGetSymbolAddress((void**)&p_h,    g_h);
    cudaGetSymbolAddress((void**)&p_xp,   g_xp);
    cudaGetSymbolAddress((void**)&p_qkv,  g_qkv);
    cudaGetSymbolAddress((void**)&p_attn, g_attn);
    cudaGetSymbolAddress((void**)&p_out,  g_out);
    cudaGetSymbolAddress((void**)&p_t1,   g_t1);
    cudaGetSymbolAddress((void**)&p_hloc, g_hloc);
    cudaGetSymbolAddress((void**)&p_cnt,  g_cnt);

    // CSR build
    cudaMemsetAsync(p_cnt, 0, Nn * sizeof(int));
    csr_hist<<<Ee / 4096, 256>>>(ei);
    csr_scan<<<1, 1024>>>();
    csr_scatter<<<(Ee + 255) / 256, 256>>>(ei);

    // input projection: h = relu(x @ w_in^T + b_in)
    gemm_tf32<<<dim3(2, 32), 256>>>(x, w_in, b_in, p_h, Hh,
                                    nullptr, nullptr, nullptr, 0, IND, 1,
                                    nullptr, nullptr, nullptr, nullptr);

    for (int l = 0; l < Ll; l++) {
        // fused GAT projection + QKV projection
        gemm_tf32<<<dim3(8, 32), 256>>>(p_h,
                                        w_gat + l * Hh * Hh, nullptr, p_xp, Hh,
                                        w_qkv + l * 3 * Hh * Hh, b_qkv + l * 3 * Hh, p_qkv, 3 * Hh,
                                        Hh, 0, nullptr, nullptr, nullptr, nullptr);
        att_logits<<<(Nn * NHEADS + 127) / 128, 128>>>(att_src + l * Hh, att_dst + l * Hh);

        // FAT kernel: flash attention (1024 blocks, first) + GAT aggregation (4096 blocks)
        gat_flash<<<FLASHBLK + Nn, 128>>>(b_gat + l * Hh,
                                          bn_g + (l * 3 + 0) * Hh, bn_b + (l * 3 + 0) * Hh);
        flash_merge<<<(NQH * DHd + 255) / 256, 256>>>();

        // w_o GEMM with fused combine_att epilogue -> g_out
        gemm_tf32<<<dim3(2, 32), 256>>>(p_attn, w_o + l * Hh * Hh, b_o + l * Hh, p_out, Hh,
                                        nullptr, nullptr, nullptr, 0, Hh, 2,
                                        p_hloc, p_h,
                                        bn_g + (l * 3 + 1) * Hh, bn_b + (l * 3 + 1) * Hh);

        // MLP
        gemm_tf32<<<dim3(4, 32), 256>>>(p_out, w1 + l * 2 * Hh * Hh, b1 + l * 2 * Hh, p_t1, 2 * Hh,
                                        nullptr, nullptr, nullptr, 0, Hh, 1,
                                        nullptr, nullptr, nullptr, nullptr);
        // w2 GEMM with fused final_combine epilogue -> g_h
        gemm_tf32<<<dim3(2, 32), 256>>>(p_t1, w2 + l * 2 * Hh * Hh, b2 + l * Hh, p_h, Hh,
                                        nullptr, nullptr, nullptr, 0, 2 * Hh, 3,
                                        p_out, p_h,
                                        bn_g + (l * 3 + 2) * Hh, bn_b + (l * 3 + 2) * Hh);
    }

    // output projection -> [4096, 2] (scalar path, M=2)
    gemm_nt<<<dim3(1, 64), dim3(16, 16)>>>(p_h, w_out, b_out, out, 2, Nn, Hh);
}